// round 7
// baseline (speedup 1.0000x reference)
#include <cuda_runtime.h>
#include <cuda_bf16.h>
#include <cstdint>

#define S_LEN 2048
#define D_DIM 512
#define NH 8
#define NROWS 4096   // B*S
#define NBH 16       // B*H

// ---------------- scratch (static device globals; no allocs) ----------------
__device__ float g_g[D_DIM];
__device__ float2 g_cu[NBH * S_LEN];                               // {cn, u}
__device__ __align__(128) int8_t g_Qh8[NBH * S_LEN * 64];          // head-major hi byte
__device__ __align__(128) int8_t g_Ql8[NBH * S_LEN * 64];          // lo byte
__device__ __align__(128) __nv_bfloat16 g_Xhi[NROWS * D_DIM];      // row-major
__device__ __align__(128) __nv_bfloat16 g_Xlo[NROWS * D_DIM];
__device__ __align__(128) __nv_bfloat16 g_Whi[D_DIM * D_DIM];      // [n][k]
__device__ __align__(128) __nv_bfloat16 g_Wlo[D_DIM * D_DIM];      // [n][k]
__device__ __align__(128) float g_Wt[D_DIM * D_DIM];               // [n][k] fp32

// ---------------- helpers ----------------
__device__ __forceinline__ float ex2(float x) {
    float r; asm("ex2.approx.ftz.f32 %0, %1;" : "=f"(r) : "f"(x)); return r;
}
__device__ __forceinline__ uint32_t smem_u32(const void* p) {
    uint32_t a;
    asm("{ .reg .u64 t; cvta.to.shared.u64 t, %1; cvt.u32.u64 %0, t; }" : "=r"(a) : "l"(p));
    return a;
}
#define LOG2E 1.4426950408889634f
#define SW128(o) ((o) ^ ((((uint32_t)(o)) >> 3) & 0x70))

__device__ __forceinline__ void ldsm4(uint32_t* r, uint32_t addr) {
    asm volatile("ldmatrix.sync.aligned.m8n8.x4.shared.b16 {%0,%1,%2,%3}, [%4];"
                 : "=r"(r[0]), "=r"(r[1]), "=r"(r[2]), "=r"(r[3]) : "r"(addr));
}
__device__ __forceinline__ void mma16816(float* c, const uint32_t* a, const uint32_t* b) {
    asm volatile("mma.sync.aligned.m16n8k16.row.col.f32.bf16.bf16.f32 "
                 "{%0,%1,%2,%3}, {%4,%5,%6,%7}, {%8,%9}, {%0,%1,%2,%3};"
                 : "+f"(c[0]), "+f"(c[1]), "+f"(c[2]), "+f"(c[3])
                 : "r"(a[0]), "r"(a[1]), "r"(a[2]), "r"(a[3]), "r"(b[0]), "r"(b[1]));
}
__device__ __forceinline__ void mma_s8(int* c, const uint32_t* a, const uint32_t* b) {
    asm volatile("mma.sync.aligned.m16n8k32.row.col.s32.s8.s8.s32 "
                 "{%0,%1,%2,%3}, {%4,%5,%6,%7}, {%8,%9}, {%0,%1,%2,%3};"
                 : "+r"(c[0]), "+r"(c[1]), "+r"(c[2]), "+r"(c[3])
                 : "r"(a[0]), "r"(a[1]), "r"(a[2]), "r"(a[3]), "r"(b[0]), "r"(b[1]));
}
__device__ __forceinline__ void cp16(uint32_t dst, const void* src) {
    asm volatile("cp.async.cg.shared.global [%0], [%1], 16;" :: "r"(dst), "l"(src));
}
__device__ __forceinline__ void cp_commit() {
    asm volatile("cp.async.commit_group;" ::: "memory");
}
template <int N>
__device__ __forceinline__ void cp_wait() {
    asm volatile("cp.async.wait_group %0;" :: "n"(N) : "memory");
}
__device__ __forceinline__ uint32_t packhl(float a, float b, uint32_t& lo) {
    __nv_bfloat16 h0 = __float2bfloat16(a);
    __nv_bfloat16 h1 = __float2bfloat16(b);
    __nv_bfloat162 hh; hh.x = h0; hh.y = h1;
    __nv_bfloat162 ll;
    ll.x = __float2bfloat16(a - __bfloat162float(h0));
    ll.y = __float2bfloat16(b - __bfloat162float(h1));
    lo = *(uint32_t*)&ll;
    return *(uint32_t*)&hh;
}
__device__ __forceinline__ void quant(float q, int8_t& h, int8_t& l) {
    int qi = __float2int_rn(q * 4096.0f);         // scale s = 2^-12
    qi = max(-32640, min(32511, qi));
    int hh = (qi + 128) >> 8;                     // round-half-up to nearest 256
    h = (int8_t)hh;
    l = (int8_t)(qi - (hh << 8));                 // in [-128, 127]
}

// ---------------- convert_w: W[k][n] -> Wt/Whi/Wlo [n][k] ----------------
__global__ __launch_bounds__(256) void convert_w(const float* __restrict__ W) {
    __shared__ float tile[32][33];
    int k0 = (blockIdx.x & 15) * 32;
    int n0 = (blockIdx.x >> 4) * 32;
    int tid = threadIdx.x;
    int r = tid >> 5, c = tid & 31;
#pragma unroll
    for (int p = 0; p < 4; p++)
        tile[p * 8 + r][c] = W[(size_t)(k0 + p * 8 + r) * 512 + n0 + c];
    __syncthreads();
#pragma unroll
    for (int p = 0; p < 4; p++) {
        int nr = p * 8 + r;
        float v = tile[c][nr];
        size_t o = (size_t)(n0 + nr) * 512 + k0 + c;
        g_Wt[o] = v;
        __nv_bfloat16 h = __float2bfloat16(v);
        g_Whi[o] = h;
        g_Wlo[o] = __float2bfloat16(v - __bfloat162float(h));
    }
}

// ---------------- calc_g: g[c] = sum_k W[k][c]*Wv[k] ----------------------
__global__ __launch_bounds__(256) void calc_g(const float* __restrict__ Wv) {
    int warp = blockIdx.x * 8 + (threadIdx.x >> 5);   // 512
    int lane = threadIdx.x & 31;
    const float* wt = g_Wt + (size_t)warp * 512;
    float a = 0.f;
#pragma unroll
    for (int m = 0; m < 16; m++) {
        int k = lane + 32 * m;
        a = fmaf(wt[k], Wv[k], a);
    }
#pragma unroll
    for (int o = 16; o > 0; o >>= 1) a += __shfl_xor_sync(0xffffffffu, a, o);
    if (lane == 0) g_g[warp] = a;
}

// ---------------- convert_x: pure streaming fp32 -> bf16 hi/lo ------------
__global__ __launch_bounds__(256) void convert_x(const float* __restrict__ X) {
    int gid = blockIdx.x * 256 + threadIdx.x;    // 262144 threads total
    const float4* src = (const float4*)X;
    uint2* dh = (uint2*)g_Xhi;
    uint2* dl = (uint2*)g_Xlo;
#pragma unroll
    for (int r = 0; r < 2; r++) {
        int i = gid * 2 + r;
        float4 v = src[i];
        uint2 hi, lo;
        hi.x = packhl(v.x, v.y, lo.x);
        hi.y = packhl(v.z, v.w, lo.y);
        dh[i] = hi;
        dl[i] = lo;
    }
}

// ---------------- gemm_q (HMMA): Q = X@W, fused norm+u+int8 emit ----------
#define GQ_STAGE 49152
#define GQ_AHI 0
#define GQ_ALO 16384
#define GQ_BHI 32768
#define GQ_BLO 40960
#define GQ_SMEM (2 * GQ_STAGE)

__device__ __forceinline__ void gq_load(uint32_t base,
        const __nv_bfloat16* Ah, const __nv_bfloat16* Al,
        const __nv_bfloat16* Bh, const __nv_bfloat16* Bl,
        int kc, int tid) {
#pragma unroll
    for (int q = 0; q < 4; q++) {
        int idx = q * 256 + tid;
        int row = idx >> 3, cg = idx & 7;
        uint32_t so = SW128((uint32_t)idx * 16);
        cp16(base + GQ_AHI + so, Ah + (size_t)row * 512 + kc + cg * 8);
        cp16(base + GQ_ALO + so, Al + (size_t)row * 512 + kc + cg * 8);
    }
#pragma unroll
    for (int q = 0; q < 2; q++) {
        int idx = q * 256 + tid;
        int row = idx >> 3, cg = idx & 7;
        uint32_t so = SW128((uint32_t)idx * 16);
        cp16(base + GQ_BHI + so, Bh + (size_t)row * 512 + kc + cg * 8);
        cp16(base + GQ_BLO + so, Bl + (size_t)row * 512 + kc + cg * 8);
    }
}

__global__ __launch_bounds__(256, 2) void gemm_q() {
    extern __shared__ char sm[];
    uint32_t sb = smem_u32(sm);
    int tid = threadIdx.x, lane = tid & 31, w = tid >> 5;
    int bid = blockIdx.x;
    int r0 = (bid >> 3) * 128;
    int h = bid & 7;
    int b = r0 >> 11, srow0 = r0 & 2047;
    const __nv_bfloat16* Ah = g_Xhi + (size_t)r0 * 512;
    const __nv_bfloat16* Al = g_Xlo + (size_t)r0 * 512;
    const __nv_bfloat16* Bh = g_Whi + (size_t)h * 64 * 512;
    const __nv_bfloat16* Bl = g_Wlo + (size_t)h * 64 * 512;

    int row_a = w * 16 + (lane & 15);
    uint32_t a_sw = (uint32_t)((row_a & 7) << 4);
    uint32_t a_hi16 = (uint32_t)((lane >> 4) * 16);
    int nrow_base = (lane & 7) + ((lane >> 4) << 3);
    uint32_t b_sw = (uint32_t)((lane & 7) << 4);
    uint32_t b_c16 = (uint32_t)(((lane >> 3) & 1) * 16);

    float cacc[8][4];
#pragma unroll
    for (int nb = 0; nb < 8; nb++)
#pragma unroll
        for (int r = 0; r < 4; r++) cacc[nb][r] = 0.f;

    gq_load(sb, Ah, Al, Bh, Bl, 0, tid);
    cp_commit();

    for (int i = 0; i < 8; i++) {
        int buf = i & 1;
        __syncthreads();
        if (i < 7) {
            gq_load(sb + (buf ^ 1) * GQ_STAGE, Ah, Al, Bh, Bl, (i + 1) * 64, tid);
            cp_commit();
            cp_wait<1>();
        } else {
            cp_wait<0>();
        }
        __syncthreads();
        uint32_t aHiB = sb + buf * GQ_STAGE + GQ_AHI + (uint32_t)row_a * 128;
        uint32_t aLoB = sb + buf * GQ_STAGE + GQ_ALO + (uint32_t)row_a * 128;
        uint32_t bHiB = sb + buf * GQ_STAGE + GQ_BHI;
        uint32_t bLoB = sb + buf * GQ_STAGE + GQ_BLO;
#pragma unroll
        for (int kk = 0; kk < 4; kk++) {
            uint32_t acol = ((uint32_t)(kk * 32) + a_hi16) ^ a_sw;
            uint32_t ahi[4], alo[4];
            ldsm4(ahi, aHiB + acol);
            ldsm4(alo, aLoB + acol);
            uint32_t bcol = ((uint32_t)(kk * 32) + b_c16) ^ b_sw;
#pragma unroll
            for (int nb2 = 0; nb2 < 4; nb2++) {
                uint32_t boff = (uint32_t)(nrow_base + nb2 * 16) * 128 + bcol;
                uint32_t bhi[4], blo[4];
                ldsm4(bhi, bHiB + boff);
                ldsm4(blo, bLoB + boff);
                mma16816(cacc[2 * nb2],     ahi, bhi);
                mma16816(cacc[2 * nb2],     ahi, blo);
                mma16816(cacc[2 * nb2],     alo, bhi);
                mma16816(cacc[2 * nb2 + 1], ahi, bhi + 2);
                mma16816(cacc[2 * nb2 + 1], ahi, blo + 2);
                mma16816(cacc[2 * nb2 + 1], alo, bhi + 2);
            }
        }
    }
    __syncthreads();   // compute done; smem reusable

    // ---- norms + u (fp32, from register Q) ----
    float sA = 0.f, sB = 0.f, uA = 0.f, uB = 0.f;
#pragma unroll
    for (int nb = 0; nb < 8; nb++) {
        int c0 = nb * 8 + (lane & 3) * 2;
        float2 gg = *(const float2*)&g_g[h * 64 + c0];
        sA = fmaf(cacc[nb][0], cacc[nb][0], sA);
        sA = fmaf(cacc[nb][1], cacc[nb][1], sA);
        sB = fmaf(cacc[nb][2], cacc[nb][2], sB);
        sB = fmaf(cacc[nb][3], cacc[nb][3], sB);
        uA = fmaf(cacc[nb][0], gg.x, uA);
        uA = fmaf(cacc[nb][1], gg.y, uA);
        uB = fmaf(cacc[nb][2], gg.x, uB);
        uB = fmaf(cacc[nb][3], gg.y, uB);
    }
#pragma unroll
    for (int o = 1; o <= 2; o <<= 1) {
        sA += __shfl_xor_sync(0xffffffffu, sA, o);
        sB += __shfl_xor_sync(0xffffffffu, sB, o);
        uA += __shfl_xor_sync(0xffffffffu, uA, o);
        uB += __shfl_xor_sync(0xffffffffu, uB, o);
    }
    int rA = w * 16 + (lane >> 2);
    if ((lane & 3) == 0) {
        int base = (b * 8 + h) * S_LEN + srow0;
        g_cu[base + rA]     = make_float2(-0.125f * LOG2E * sqrtf(sA), uA);
        g_cu[base + rA + 8] = make_float2(-0.125f * LOG2E * sqrtf(sB), uB);
    }

    // ---- quantize Q -> int8 h/l planes, staged via smem [128][68] --------
    int8_t* sH = (int8_t*)sm;
    int8_t* sL = (int8_t*)(sm + 128 * 68);
#pragma unroll
    for (int nb = 0; nb < 8; nb++) {
        int c0 = nb * 8 + (lane & 3) * 2;
        int8_t h0, l0, h1, l1;
        quant(cacc[nb][0], h0, l0); quant(cacc[nb][1], h1, l1);
        sH[rA * 68 + c0] = h0; sH[rA * 68 + c0 + 1] = h1;
        sL[rA * 68 + c0] = l0; sL[rA * 68 + c0 + 1] = l1;
        quant(cacc[nb][2], h0, l0); quant(cacc[nb][3], h1, l1);
        sH[(rA + 8) * 68 + c0] = h0; sH[(rA + 8) * 68 + c0 + 1] = h1;
        sL[(rA + 8) * 68 + c0] = l0; sL[(rA + 8) * 68 + c0 + 1] = l1;
    }
    __syncthreads();
    uint32_t* dH = (uint32_t*)(g_Qh8 + ((size_t)(b * 8 + h) * S_LEN + srow0) * 64);
    uint32_t* dL = (uint32_t*)(g_Ql8 + ((size_t)(b * 8 + h) * S_LEN + srow0) * 64);
#pragma unroll
    for (int q = 0; q < 8; q++) {
        int i = q * 256 + tid;           // 2048 u32 per plane
        int row = i >> 4, c = i & 15;
        dH[row * 16 + c] = *(const uint32_t*)(sH + row * 68 + c * 4);
        dL[row * 16 + c] = *(const uint32_t*)(sL + row * 68 + c * 4);
    }
}

// ---------------- fused attention (int8 16-bit split MMA) -----------------
// smem: QS 16K | QT[2] 16K each | CU[2] 1K each = 51200 B
#define AT_QS 0
#define AT_QT 16384
#define AT_CU 49152
#define ATTN_SMEM_BYTES 51200

__global__ __launch_bounds__(256, 2) void attn(float* __restrict__ out) {
    extern __shared__ char sm[];
    uint32_t sb = smem_u32(sm);
    int tid = threadIdx.x;
    int lane = tid & 31, w = tid >> 5;
    int bid = blockIdx.x;
    int stile = bid & 15;
    int bh = bid >> 4;
    int s0 = stile * 128;
    int bhS = bh * S_LEN;

    const int8_t* qhB = g_Qh8 + (size_t)bhS * 64;
    const int8_t* qlB = g_Ql8 + (size_t)bhS * 64;

    // ---- load QS (resident): rows = [64B h | 64B l], SW128 ----
    {
        const uint4* sh = (const uint4*)(qhB + (size_t)s0 * 64);
        const uint4* sl = (const uint4*)(qlB + (size_t)s0 * 64);
#pragma unroll
        for (int q = 0; q < 4; q++) {
            int idx = q * 256 + tid;             // 0..1023
            int row = idx >> 3, p = (idx >> 2) & 1, sub = idx & 3;
            uint32_t so = SW128((uint32_t)(row * 128 + p * 64 + sub * 16));
            *(uint4*)(sm + AT_QS + so) = p ? sl[row * 4 + sub] : sh[row * 4 + sub];
        }
    }
    // ---- prefetch tile 0 ----
    {
#pragma unroll
        for (int q = 0; q < 4; q++) {
            int idx = q * 256 + tid;
            int row = idx >> 3, p = (idx >> 2) & 1, sub = idx & 3;
            uint32_t so = SW128((uint32_t)(row * 128 + p * 64 + sub * 16));
            const int8_t* src = (p ? qlB : qhB) + (size_t)row * 64 + sub * 16;
            cp16(sb + AT_QT + so, src);
        }
        if (tid < 64) cp16(sb + AT_CU + tid * 16, (const char*)(g_cu + bhS) + tid * 16);
        cp_commit();
    }

    int row_a = w * 16 + (lane & 15);
    uint32_t a_sw = (uint32_t)((row_a & 7) << 4);
    uint32_t a_hi16 = (uint32_t)((lane >> 4) * 16);
    uint32_t aBase = sb + AT_QS + (uint32_t)row_a * 128;
    int nrow_base = (lane & 7) + ((lane >> 4) << 3);
    uint32_t b_sw = (uint32_t)((lane & 7) << 4);
    uint32_t b_c16 = (uint32_t)(((lane >> 3) & 1) * 16);

    const float C1 = 0.25f * LOG2E;
    const float K1 = C1 * (1.0f / 256.0f);      // 2^16 * s^2 * C1,  s = 2^-12
    const float K2 = C1 * (1.0f / 65536.0f);    // 2^8  * s^2 * C1
    float den0 = 0.f, num0 = 0.f, den1 = 0.f, num1 = 0.f;

    for (int it = 0; it < 16; it++) {
        int buf = it & 1;
        __syncthreads();
        if (it < 15) {
            int t1 = (it + 1) * 128;
            uint32_t base = sb + AT_QT + (buf ^ 1) * 16384;
#pragma unroll
            for (int q = 0; q < 4; q++) {
                int idx = q * 256 + tid;
                int row = idx >> 3, p = (idx >> 2) & 1, sub = idx & 3;
                uint32_t so = SW128((uint32_t)(row * 128 + p * 64 + sub * 16));
                const int8_t* src = (p ? qlB : qhB) + (size_t)(t1 + row) * 64 + sub * 16;
                cp16(base + so, src);
            }
            if (tid < 64)
                cp16(sb + AT_CU + (buf ^ 1) * 1024 + tid * 16,
                     (const char*)(g_cu + bhS + t1) + tid * 16);
            cp_commit();
            cp_wait<1>();
        } else {
            cp_wait<0>();
        }
        __syncthreads();

        uint32_t btB = sb + AT_QT + buf * 16384;
        const float2* scu = (const float2*)(sm + AT_CU + buf * 1024);

        // A fragments for all 4 32-byte k-groups (g0,g1 = h; g2,g3 = l)
        uint32_t afr[4][4];
#pragma unroll
        for (int g = 0; g < 4; g++)
            ldsm4(afr[g], aBase + (((uint32_t)(g * 32) + a_hi16) ^ a_sw));

#pragma unroll
        for (int qtr = 0; qtr < 4; qtr++) {      // 32 t-columns per quarter
            int accH[4][4], accX[4][4];
#pragma unroll
            for (int i = 0; i < 4; i++)
#pragma unroll
                for (int r = 0; r < 4; r++) { accH[i][r] = 0; accX[i][r] = 0; }

#pragma unroll
            for (int nb2 = 0; nb2 < 2; nb2++) {
                uint32_t nrow = (uint32_t)(nrow_base + (qtr * 2 + nb2) * 16);
                uint32_t bfr[4][4];
#pragma unroll
                for (int g = 0; g < 4; g++)
                    ldsm4(bfr[g], btB + nrow * 128 + (((uint32_t)(g * 32) + b_c16) ^ b_sw));
#pragma unroll
                for (int nblk = 0; nblk < 2; nblk++) {
                    int* H = accH[nb2 * 2 + nblk];
                    int* Xc = accX[nb2 * 2 + nblk];
                    const uint32_t* b0 = bfr[0] + 2 * nblk;
                    const uint32_t* b1 = bfr[1] + 2 * nblk;
                    const uint32_t* b2 = bfr[2] + 2 * nblk;
                    const uint32_t* b3 = bfr[3] + 2 * nblk;
                    mma_s8(H,  afr[0], b0);   // h.h  (k 0-31)
                    mma_s8(H,  afr[1], b1);   // h.h  (k 32-63)
                    mma_s8(Xc, afr[0], b2);   // h.l
                    mma_s8(Xc, afr[1], b3);   // h.l
                    mma_s8(Xc, afr[2], b0);   // l.h
                    mma_s8(Xc, afr[3], b1);   // l.h
                }
            }

            // ---- epilogue for this quarter ----
#pragma unroll
            for (int i = 0; i < 4; i++) {
                int col0 = (qtr * 4 + i) * 8 + (lane & 3) * 2;
                float2 cuA = scu[col0];
                float2 cuB = scu[col0 + 1];
                float w0 = ex2(fmaf(K1, (float)accH[i][0], fmaf(K2, (float)accX[i][0], cuA.x)));
                float w1 = ex2(fmaf(K1, (float)accH[i][1], fmaf(K2, (float)accX[i][1], cuB.x)));
                float w2 = ex2(fmaf(K1, (float)accH[i][2], fmaf(K2, (float)accX[i][2], cuA.x)));
                float w3 = ex2(fmaf(K1, (float)accH[i][3], fmaf(K2, (float)accX[i][3], cuB.x)));
                den0 += w0; num0 = fmaf(w0, cuA.y, num0);
                den0 += w1; num0 = fmaf(w1, cuB.y, num0);
                den1 += w2; num1 = fmaf(w2, cuA.y, num1);
                den1 += w3; num1 = fmaf(w3, cuB.y, num1);
            }
        }
    }

    // quad reduction
#pragma unroll
    for (int o = 1; o <= 2; o <<= 1) {
        den0 += __shfl_xor_sync(0xffffffffu, den0, o);
        num0 += __shfl_xor_sync(0xffffffffu, num0, o);
        den1 += __shfl_xor_sync(0xffffffffu, den1, o);
        num1 += __shfl_xor_sync(0xffffffffu, num1, o);
    }
    if ((lane & 3) == 0) {
        int gr = lane >> 2;
        int r0 = w * 16 + gr;
        float z0 = num0 / den0;
        float z1 = num1 / den1;
        out[bhS + s0 + r0]     = 1.0f / (1.0f + ex2(-z0 * LOG2E));
        out[bhS + s0 + r0 + 8] = 1.0f / (1.0f + ex2(-z1 * LOG2E));
    }
}

// ---------------- launch ----------------
extern "C" void kernel_launch(void* const* d_in, const int* in_sizes, int n_in,
                              void* d_out, int out_size) {
    const float *X = nullptr, *Wq = nullptr, *Wv = nullptr;
    for (int i = 0; i < n_in; i++) {
        if (in_sizes[i] == 2 * 2048 * 512)      X  = (const float*)d_in[i];
        else if (in_sizes[i] == 512 * 512)      Wq = (const float*)d_in[i];
        else if (in_sizes[i] == 512)            Wv = (const float*)d_in[i];
    }
    float* out = (float*)d_out;

    cudaFuncSetAttribute(gemm_q, cudaFuncAttributeMaxDynamicSharedMemorySize, GQ_SMEM);
    cudaFuncSetAttribute(attn, cudaFuncAttributeMaxDynamicSharedMemorySize, ATTN_SMEM_BYTES);

    convert_w<<<256, 256>>>(Wq);
    calc_g<<<64, 256>>>(Wv);
    convert_x<<<1024, 256>>>(X);
    gemm_q<<<256, 256, GQ_SMEM>>>();
    attn<<<256, 256, ATTN_SMEM_BYTES>>>(out);
}

// round 8
// speedup vs baseline: 3.6648x; 3.6648x over previous
#include <cuda_runtime.h>
#include <cuda_bf16.h>
#include <cstdint>

#define S_LEN 2048
#define D_DIM 512
#define NH 8
#define NROWS 4096   // B*S
#define NBH 16       // B*H

// ---------------- scratch (static device globals; no allocs) ----------------
__device__ float g_g[D_DIM];
__device__ float2 g_cu[NBH * S_LEN];                               // {cn, u}
__device__ __align__(128) __nv_bfloat16 g_Qhi[NBH * S_LEN * 64];   // head-major
__device__ __align__(128) __nv_bfloat16 g_Qlo[NBH * S_LEN * 64];
__device__ __align__(128) __nv_bfloat16 g_Xhi[NROWS * D_DIM];      // row-major
__device__ __align__(128) __nv_bfloat16 g_Xlo[NROWS * D_DIM];
__device__ __align__(128) __nv_bfloat16 g_Whi[D_DIM * D_DIM];      // [n][k]
__device__ __align__(128) __nv_bfloat16 g_Wlo[D_DIM * D_DIM];      // [n][k]
__device__ __align__(128) float g_Wt[D_DIM * D_DIM];               // [n][k] fp32

// ---------------- helpers ----------------
__device__ __forceinline__ float ex2(float x) {
    float r; asm("ex2.approx.ftz.f32 %0, %1;" : "=f"(r) : "f"(x)); return r;
}
__device__ __forceinline__ uint32_t smem_u32(const void* p) {
    uint32_t a;
    asm("{ .reg .u64 t; cvta.to.shared.u64 t, %1; cvt.u32.u64 %0, t; }" : "=r"(a) : "l"(p));
    return a;
}
#define LOG2E 1.4426950408889634f
#define SW128(o) ((o) ^ ((((uint32_t)(o)) >> 3) & 0x70))

__device__ __forceinline__ void ldsm4(uint32_t* r, uint32_t addr) {
    asm volatile("ldmatrix.sync.aligned.m8n8.x4.shared.b16 {%0,%1,%2,%3}, [%4];"
                 : "=r"(r[0]), "=r"(r[1]), "=r"(r[2]), "=r"(r[3]) : "r"(addr));
}
__device__ __forceinline__ void mma16816(float* c, const uint32_t* a, const uint32_t* b) {
    asm volatile("mma.sync.aligned.m16n8k16.row.col.f32.bf16.bf16.f32 "
                 "{%0,%1,%2,%3}, {%4,%5,%6,%7}, {%8,%9}, {%0,%1,%2,%3};"
                 : "+f"(c[0]), "+f"(c[1]), "+f"(c[2]), "+f"(c[3])
                 : "r"(a[0]), "r"(a[1]), "r"(a[2]), "r"(a[3]), "r"(b[0]), "r"(b[1]));
}
__device__ __forceinline__ void cp16(uint32_t dst, const void* src) {
    asm volatile("cp.async.cg.shared.global [%0], [%1], 16;" :: "r"(dst), "l"(src));
}
__device__ __forceinline__ void cp_commit() {
    asm volatile("cp.async.commit_group;" ::: "memory");
}
template <int N>
__device__ __forceinline__ void cp_wait() {
    asm volatile("cp.async.wait_group %0;" :: "n"(N) : "memory");
}
__device__ __forceinline__ uint32_t packhl(float a, float b, uint32_t& lo) {
    __nv_bfloat16 h0 = __float2bfloat16(a);
    __nv_bfloat16 h1 = __float2bfloat16(b);
    __nv_bfloat162 hh; hh.x = h0; hh.y = h1;
    __nv_bfloat162 ll;
    ll.x = __float2bfloat16(a - __bfloat162float(h0));
    ll.y = __float2bfloat16(b - __bfloat162float(h1));
    lo = *(uint32_t*)&ll;
    return *(uint32_t*)&hh;
}

// ---------------- convert_w: W[k][n] -> Wt/Whi/Wlo [n][k] ----------------
__global__ __launch_bounds__(256) void convert_w(const float* __restrict__ W) {
    __shared__ float tile[32][33];
    int k0 = (blockIdx.x & 15) * 32;
    int n0 = (blockIdx.x >> 4) * 32;
    int tid = threadIdx.x;
    int r = tid >> 5, c = tid & 31;
#pragma unroll
    for (int p = 0; p < 4; p++)
        tile[p * 8 + r][c] = W[(size_t)(k0 + p * 8 + r) * 512 + n0 + c];
    __syncthreads();
#pragma unroll
    for (int p = 0; p < 4; p++) {
        int nr = p * 8 + r;
        float v = tile[c][nr];
        size_t o = (size_t)(n0 + nr) * 512 + k0 + c;
        g_Wt[o] = v;
        __nv_bfloat16 h = __float2bfloat16(v);
        g_Whi[o] = h;
        g_Wlo[o] = __float2bfloat16(v - __bfloat162float(h));
    }
}

// ---------------- calc_g: g[c] = sum_k W[k][c]*Wv[k] ----------------------
__global__ __launch_bounds__(256) void calc_g(const float* __restrict__ Wv) {
    int warp = blockIdx.x * 8 + (threadIdx.x >> 5);   // 512
    int lane = threadIdx.x & 31;
    const float* wt = g_Wt + (size_t)warp * 512;
    float a = 0.f;
#pragma unroll
    for (int m = 0; m < 16; m++) {
        int k = lane + 32 * m;
        a = fmaf(wt[k], Wv[k], a);
    }
#pragma unroll
    for (int o = 16; o > 0; o >>= 1) a += __shfl_xor_sync(0xffffffffu, a, o);
    if (lane == 0) g_g[warp] = a;
}

// ---------------- convert_x: pure streaming fp32 -> bf16 hi/lo ------------
__global__ __launch_bounds__(256) void convert_x(const float* __restrict__ X) {
    int gid = blockIdx.x * 256 + threadIdx.x;    // 262144 threads total
    const float4* src = (const float4*)X;
    uint2* dh = (uint2*)g_Xhi;
    uint2* dl = (uint2*)g_Xlo;
#pragma unroll
    for (int r = 0; r < 2; r++) {
        int i = gid * 2 + r;
        float4 v = src[i];
        uint2 hi, lo;
        hi.x = packhl(v.x, v.y, lo.x);
        hi.y = packhl(v.z, v.w, lo.y);
        dh[i] = hi;
        dl[i] = lo;
    }
}

// ---------------- gemm_q (HMMA): Q = X@W, fused norm + u + bf16 emit ------
#define GQ_STAGE 49152
#define GQ_AHI 0
#define GQ_ALO 16384
#define GQ_BHI 32768
#define GQ_BLO 40960
#define GQ_SMEM (2 * GQ_STAGE)

__device__ __forceinline__ void gq_load(uint32_t base,
        const __nv_bfloat16* Ah, const __nv_bfloat16* Al,
        const __nv_bfloat16* Bh, const __nv_bfloat16* Bl,
        int kc, int tid) {
#pragma unroll
    for (int q = 0; q < 4; q++) {
        int idx = q * 256 + tid;
        int row = idx >> 3, cg = idx & 7;
        uint32_t so = SW128((uint32_t)idx * 16);
        cp16(base + GQ_AHI + so, Ah + (size_t)row * 512 + kc + cg * 8);
        cp16(base + GQ_ALO + so, Al + (size_t)row * 512 + kc + cg * 8);
    }
#pragma unroll
    for (int q = 0; q < 2; q++) {
        int idx = q * 256 + tid;
        int row = idx >> 3, cg = idx & 7;
        uint32_t so = SW128((uint32_t)idx * 16);
        cp16(base + GQ_BHI + so, Bh + (size_t)row * 512 + kc + cg * 8);
        cp16(base + GQ_BLO + so, Bl + (size_t)row * 512 + kc + cg * 8);
    }
}

__global__ __launch_bounds__(256, 2) void gemm_q() {
    extern __shared__ char sm[];
    uint32_t sb = smem_u32(sm);
    int tid = threadIdx.x, lane = tid & 31, w = tid >> 5;
    int bid = blockIdx.x;
    int r0 = (bid >> 3) * 128;
    int h = bid & 7;
    int b = r0 >> 11, srow0 = r0 & 2047;
    const __nv_bfloat16* Ah = g_Xhi + (size_t)r0 * 512;
    const __nv_bfloat16* Al = g_Xlo + (size_t)r0 * 512;
    const __nv_bfloat16* Bh = g_Whi + (size_t)h * 64 * 512;
    const __nv_bfloat16* Bl = g_Wlo + (size_t)h * 64 * 512;

    int row_a = w * 16 + (lane & 15);
    uint32_t a_sw = (uint32_t)((row_a & 7) << 4);
    uint32_t a_hi16 = (uint32_t)((lane >> 4) * 16);
    int nrow_base = (lane & 7) + ((lane >> 4) << 3);
    uint32_t b_sw = (uint32_t)((lane & 7) << 4);
    uint32_t b_c16 = (uint32_t)(((lane >> 3) & 1) * 16);

    float cacc[8][4];
#pragma unroll
    for (int nb = 0; nb < 8; nb++)
#pragma unroll
        for (int r = 0; r < 4; r++) cacc[nb][r] = 0.f;

    gq_load(sb, Ah, Al, Bh, Bl, 0, tid);
    cp_commit();

    for (int i = 0; i < 8; i++) {
        int buf = i & 1;
        __syncthreads();
        if (i < 7) {
            gq_load(sb + (buf ^ 1) * GQ_STAGE, Ah, Al, Bh, Bl, (i + 1) * 64, tid);
            cp_commit();
            cp_wait<1>();
        } else {
            cp_wait<0>();
        }
        __syncthreads();
        uint32_t aHiB = sb + buf * GQ_STAGE + GQ_AHI + (uint32_t)row_a * 128;
        uint32_t aLoB = sb + buf * GQ_STAGE + GQ_ALO + (uint32_t)row_a * 128;
        uint32_t bHiB = sb + buf * GQ_STAGE + GQ_BHI;
        uint32_t bLoB = sb + buf * GQ_STAGE + GQ_BLO;
#pragma unroll
        for (int kk = 0; kk < 4; kk++) {
            uint32_t acol = ((uint32_t)(kk * 32) + a_hi16) ^ a_sw;
            uint32_t ahi[4], alo[4];
            ldsm4(ahi, aHiB + acol);
            ldsm4(alo, aLoB + acol);
            uint32_t bcol = ((uint32_t)(kk * 32) + b_c16) ^ b_sw;
#pragma unroll
            for (int nb2 = 0; nb2 < 4; nb2++) {
                uint32_t boff = (uint32_t)(nrow_base + nb2 * 16) * 128 + bcol;
                uint32_t bhi[4], blo[4];
                ldsm4(bhi, bHiB + boff);
                ldsm4(blo, bLoB + boff);
                mma16816(cacc[2 * nb2],     ahi, bhi);
                mma16816(cacc[2 * nb2],     ahi, blo);
                mma16816(cacc[2 * nb2],     alo, bhi);
                mma16816(cacc[2 * nb2 + 1], ahi, bhi + 2);
                mma16816(cacc[2 * nb2 + 1], ahi, blo + 2);
                mma16816(cacc[2 * nb2 + 1], alo, bhi + 2);
            }
        }
    }
    __syncthreads();   // compute done; smem reusable

    // ---- norms + u = Q.g (fp32, from register Q) ----
    float sA = 0.f, sB = 0.f, uA = 0.f, uB = 0.f;
#pragma unroll
    for (int nb = 0; nb < 8; nb++) {
        int c0 = nb * 8 + (lane & 3) * 2;
        float2 gg = *(const float2*)&g_g[h * 64 + c0];
        sA = fmaf(cacc[nb][0], cacc[nb][0], sA);
        sA = fmaf(cacc[nb][1], cacc[nb][1], sA);
        sB = fmaf(cacc[nb][2], cacc[nb][2], sB);
        sB = fmaf(cacc[nb][3], cacc[nb][3], sB);
        uA = fmaf(cacc[nb][0], gg.x, uA);
        uA = fmaf(cacc[nb][1], gg.y, uA);
        uB = fmaf(cacc[nb][2], gg.x, uB);
        uB = fmaf(cacc[nb][3], gg.y, uB);
    }
#pragma unroll
    for (int o = 1; o <= 2; o <<= 1) {
        sA += __shfl_xor_sync(0xffffffffu, sA, o);
        sB += __shfl_xor_sync(0xffffffffu, sB, o);
        uA += __shfl_xor_sync(0xffffffffu, uA, o);
        uB += __shfl_xor_sync(0xffffffffu, uB, o);
    }
    int rA = w * 16 + (lane >> 2);
    if ((lane & 3) == 0) {
        int base = (b * 8 + h) * S_LEN + srow0;
        g_cu[base + rA]     = make_float2(-0.125f * LOG2E * sqrtf(sA), uA);
        g_cu[base + rA + 8] = make_float2(-0.125f * LOG2E * sqrtf(sB), uB);
    }

    // ---- stage Q hi/lo (padded [128][33] u32) ----
    uint32_t* sHi32 = (uint32_t*)sm;
    uint32_t* sLo32 = (uint32_t*)(sm + 16896);
#pragma unroll
    for (int nb = 0; nb < 8; nb++) {
        int cslot = nb * 4 + (lane & 3);
        uint32_t lo0, lo1;
        uint32_t hi0 = packhl(cacc[nb][0], cacc[nb][1], lo0);
        uint32_t hi1 = packhl(cacc[nb][2], cacc[nb][3], lo1);
        sHi32[rA * 33 + cslot] = hi0;
        sLo32[rA * 33 + cslot] = lo0;
        sHi32[(rA + 8) * 33 + cslot] = hi1;
        sLo32[(rA + 8) * 33 + cslot] = lo1;
    }
    __syncthreads();
    uint32_t* dH = (uint32_t*)(g_Qhi + ((size_t)(b * 8 + h) * S_LEN + srow0) * 64);
    uint32_t* dL = (uint32_t*)(g_Qlo + ((size_t)(b * 8 + h) * S_LEN + srow0) * 64);
#pragma unroll
    for (int q = 0; q < 16; q++) {              // 4096 u32 = 128 rows x 32
        int linear = q * 256 + tid;
        int row = linear >> 5, c = linear & 31;
        dH[row * 32 + c] = sHi32[row * 33 + c];
        dL[row * 32 + c] = sLo32[row * 33 + c];
    }
}

// ---------------- fused attention (R6 proven bf16 hi/lo version) ----------
#define OFF_QSHI 0
#define OFF_QSLO 16384
#define OFF_QT   32768
#define OFF_CU   98304
#define ATTN_SMEM_BYTES 100352

__global__ __launch_bounds__(256, 2) void attn(float* __restrict__ out) {
    extern __shared__ char sm[];
    uint32_t sb = smem_u32(sm);
    int tid = threadIdx.x;
    int lane = tid & 31, w = tid >> 5;
    int bid = blockIdx.x;
    int stile = bid & 15;
    int bh = bid >> 4;
    int s0 = stile * 128;
    int bhS = bh * S_LEN;

    const __nv_bfloat16* qhiB = g_Qhi + (size_t)bhS * 64;
    const __nv_bfloat16* qloB = g_Qlo + (size_t)bhS * 64;

    {
        const uint4* shi = (const uint4*)(qhiB + (size_t)s0 * 64);
        const uint4* slo = (const uint4*)(qloB + (size_t)s0 * 64);
#pragma unroll
        for (int q = 0; q < 4; q++) {
            uint32_t idx = (uint32_t)(q * 256 + tid);
            uint32_t so = SW128(idx * 16);
            *(uint4*)(sm + OFF_QSHI + so) = shi[idx];
            *(uint4*)(sm + OFF_QSLO + so) = slo[idx];
        }
    }
    {
        const uint4* thi = (const uint4*)qhiB;
        const uint4* tlo = (const uint4*)qloB;
#pragma unroll
        for (int q = 0; q < 4; q++) {
            uint32_t idx = (uint32_t)(q * 256 + tid);
            uint32_t so = SW128(idx * 16);
            cp16(sb + OFF_QT + so, thi + idx);
            cp16(sb + OFF_QT + 16384 + so, tlo + idx);
        }
        if (tid < 64) cp16(sb + OFF_CU + tid * 16, (const char*)(g_cu + bhS) + tid * 16);
        cp_commit();
    }

    int row_a = w * 16 + (lane & 15);
    uint32_t a_sw = (uint32_t)((row_a & 7) << 4);
    uint32_t a_hi16 = (uint32_t)((lane >> 4) * 16);
    uint32_t aBaseHi = sb + OFF_QSHI + (uint32_t)row_a * 128;
    uint32_t aBaseLo = sb + OFF_QSLO + (uint32_t)row_a * 128;
    int nrow_base = (lane & 7) + ((lane >> 4) << 3);
    uint32_t b_sw = (uint32_t)((lane & 7) << 4);
    uint32_t b_c16 = (uint32_t)(((lane >> 3) & 1) * 16);

    const float C1 = 0.25f * LOG2E;
    float den0 = 0.f, num0 = 0.f, den1 = 0.f, num1 = 0.f;

    for (int it = 0; it < 16; it++) {
        int buf = it & 1;
        __syncthreads();
        if (it < 15) {
            int t1 = (it + 1) * 128;
            const uint4* thi = (const uint4*)(qhiB + (size_t)t1 * 64);
            const uint4* tlo = (const uint4*)(qloB + (size_t)t1 * 64);
            uint32_t base = sb + OFF_QT + (buf ^ 1) * 32768;
#pragma unroll
            for (int q = 0; q < 4; q++) {
                uint32_t idx = (uint32_t)(q * 256 + tid);
                uint32_t so = SW128(idx * 16);
                cp16(base + so, thi + idx);
                cp16(base + 16384 + so, tlo + idx);
            }
            if (tid < 64)
                cp16(sb + OFF_CU + (buf ^ 1) * 1024 + tid * 16,
                     (const char*)(g_cu + bhS + t1) + tid * 16);
            cp_commit();
            cp_wait<1>();
        } else {
            cp_wait<0>();
        }
        __syncthreads();

        uint32_t btHi = sb + OFF_QT + buf * 32768;
        uint32_t btLo = btHi + 16384;
        const float2* scu = (const float2*)(sm + OFF_CU + buf * 1024);

        float cacc[16][4];
#pragma unroll
        for (int nb = 0; nb < 16; nb++)
#pragma unroll
            for (int r = 0; r < 4; r++) cacc[nb][r] = 0.f;

#pragma unroll
        for (int kk = 0; kk < 4; kk++) {
            uint32_t acol = ((uint32_t)(kk * 32) + a_hi16) ^ a_sw;
            uint32_t ahi[4], alo[4];
            ldsm4(ahi, aBaseHi + acol);
            ldsm4(alo, aBaseLo + acol);
            uint32_t bcol = ((uint32_t)(kk * 32) + b_c16) ^ b_sw;
#pragma unroll
            for (int nb2 = 0; nb2 < 8; nb2++) {
                uint32_t boff = (uint32_t)(nrow_base + nb2 * 16) * 128 + bcol;
                uint32_t bhi[4], blo[4];
                ldsm4(bhi, btHi + boff);
                ldsm4(blo, btLo + boff);
                mma16816(cacc[2 * nb2],     ahi, bhi);
                mma16816(cacc[2 * nb2],     ahi, blo);
                mma16816(cacc[2 * nb2],     alo, bhi);
                mma16816(cacc[2 * nb2 + 1], ahi, bhi + 2);
                mma16816(cacc[2 * nb2 + 1], ahi, blo + 2);
                mma16816(cacc[2 * nb2 + 1], alo, bhi + 2);
            }
        }

#pragma unroll
        for (int nb = 0; nb < 16; nb++) {
            int col0 = nb * 8 + (lane & 3) * 2;
            float2 cuA = scu[col0];
            float2 cuB = scu[col0 + 1];
            float w0 = ex2(fmaf(cacc[nb][0], C1, cuA.x));
            float w1 = ex2(fmaf(cacc[nb][1], C1, cuB.x));
            float w2 = ex2(fmaf(cacc[nb][2], C1, cuA.x));
            float w3 = ex2(fmaf(cacc[nb][3], C1, cuB.x));
            den0 += w0; num0 = fmaf(w0, cuA.y, num0);
            den0 += w1; num0 = fmaf(w1, cuB.y, num0);
            den1 += w2; num1 = fmaf(w2, cuA.y, num1);
            den1 += w3; num1 = fmaf(w3, cuB.y, num1);
        }
    }

#pragma unroll
    for (int o = 1; o <= 2; o <<= 1) {
        den0 += __shfl_xor_sync(0xffffffffu, den0, o);
        num0 += __shfl_xor_sync(0xffffffffu, num0, o);
        den1 += __shfl_xor_sync(0xffffffffu, den1, o);
        num1 += __shfl_xor_sync(0xffffffffu, num1, o);
    }
    if ((lane & 3) == 0) {
        int gr = lane >> 2;
        int r0 = w * 16 + gr;
        float z0 = num0 / den0;
        float z1 = num1 / den1;
        out[bhS + s0 + r0]     = 1.0f / (1.0f + ex2(-z0 * LOG2E));
        out[bhS + s0 + r0 + 8] = 1.0f / (1.0f + ex2(-z1 * LOG2E));
    }
}

// ---------------- launch ----------------
extern "C" void kernel_launch(void* const* d_in, const int* in_sizes, int n_in,
                              void* d_out, int out_size) {
    const float *X = nullptr, *Wq = nullptr, *Wv = nullptr;
    for (int i = 0; i < n_in; i++) {
        if (in_sizes[i] == 2 * 2048 * 512)      X  = (const float*)d_in[i];
        else if (in_sizes[i] == 512 * 512)      Wq = (const float*)d_in[i];
        else if (in_sizes[i] == 512)            Wv = (const float*)d_in[i];
    }
    float* out = (float*)d_out;

    cudaFuncSetAttribute(gemm_q, cudaFuncAttributeMaxDynamicSharedMemorySize, GQ_SMEM);
    cudaFuncSetAttribute(attn, cudaFuncAttributeMaxDynamicSharedMemorySize, ATTN_SMEM_BYTES);

    convert_w<<<256, 256>>>(Wq);
    calc_g<<<64, 256>>>(Wv);
    convert_x<<<1024, 256>>>(X);
    gemm_q<<<256, 256, GQ_SMEM>>>();
    attn<<<256, 256, ATTN_SMEM_BYTES>>>(out);
}

// round 10
// speedup vs baseline: 4.4370x; 1.2107x over previous
#include <cuda_runtime.h>
#include <cuda_bf16.h>
#include <cstdint>

#define S_LEN 2048
#define D_DIM 512
#define NH 8
#define NROWS 4096   // B*S
#define NBH 16       // B*H

// ---------------- scratch (static device globals; no allocs) ----------------
__device__ float g_g[D_DIM];
__device__ float2 g_cu[NBH * S_LEN];                               // {cn, u}
__device__ __align__(128) __nv_bfloat16 g_Qhi[NBH * S_LEN * 64];   // head-major
__device__ __align__(128) __nv_bfloat16 g_Qlo[NBH * S_LEN * 64];
__device__ __align__(128) __nv_bfloat16 g_Xhi[NROWS * D_DIM];      // row-major
__device__ __align__(128) __nv_bfloat16 g_Xlo[NROWS * D_DIM];
__device__ __align__(128) __nv_bfloat16 g_Whi[D_DIM * D_DIM];      // [n][k]
__device__ __align__(128) __nv_bfloat16 g_Wlo[D_DIM * D_DIM];      // [n][k]
__device__ __align__(128) float g_Wt[D_DIM * D_DIM];               // [n][k] fp32
__device__ __align__(128) float g_pd[NBH * S_LEN * 16];            // den partials
__device__ __align__(128) float g_pn[NBH * S_LEN * 16];            // num partials

// ---------------- helpers ----------------
__device__ __forceinline__ float ex2(float x) {
    float r; asm("ex2.approx.ftz.f32 %0, %1;" : "=f"(r) : "f"(x)); return r;
}
__device__ __forceinline__ uint32_t smem_u32(const void* p) {
    uint32_t a;
    asm("{ .reg .u64 t; cvta.to.shared.u64 t, %1; cvt.u32.u64 %0, t; }" : "=r"(a) : "l"(p));
    return a;
}
#define LOG2E 1.4426950408889634f
#define SW128(o) ((o) ^ ((((uint32_t)(o)) >> 3) & 0x70))

__device__ __forceinline__ void ldsm4(uint32_t* r, uint32_t addr) {
    asm volatile("ldmatrix.sync.aligned.m8n8.x4.shared.b16 {%0,%1,%2,%3}, [%4];"
                 : "=r"(r[0]), "=r"(r[1]), "=r"(r[2]), "=r"(r[3]) : "r"(addr));
}
__device__ __forceinline__ void mma16816(float* c, const uint32_t* a, const uint32_t* b) {
    asm volatile("mma.sync.aligned.m16n8k16.row.col.f32.bf16.bf16.f32 "
                 "{%0,%1,%2,%3}, {%4,%5,%6,%7}, {%8,%9}, {%0,%1,%2,%3};"
                 : "+f"(c[0]), "+f"(c[1]), "+f"(c[2]), "+f"(c[3])
                 : "r"(a[0]), "r"(a[1]), "r"(a[2]), "r"(a[3]), "r"(b[0]), "r"(b[1]));
}
__device__ __forceinline__ void cp16(uint32_t dst, const void* src) {
    asm volatile("cp.async.cg.shared.global [%0], [%1], 16;" :: "r"(dst), "l"(src));
}
__device__ __forceinline__ void cp_commit() {
    asm volatile("cp.async.commit_group;" ::: "memory");
}
template <int N>
__device__ __forceinline__ void cp_wait() {
    asm volatile("cp.async.wait_group %0;" :: "n"(N) : "memory");
}
__device__ __forceinline__ uint32_t packhl(float a, float b, uint32_t& lo) {
    __nv_bfloat16 h0 = __float2bfloat16(a);
    __nv_bfloat16 h1 = __float2bfloat16(b);
    __nv_bfloat162 hh; hh.x = h0; hh.y = h1;
    __nv_bfloat162 ll;
    ll.x = __float2bfloat16(a - __bfloat162float(h0));
    ll.y = __float2bfloat16(b - __bfloat162float(h1));
    lo = *(uint32_t*)&ll;
    return *(uint32_t*)&hh;
}

// ---------------- convert_w: W[k][n] -> Wt/Whi/Wlo [n][k] ----------------
__global__ __launch_bounds__(256) void convert_w(const float* __restrict__ W) {
    __shared__ float tile[32][33];
    int k0 = (blockIdx.x & 15) * 32;
    int n0 = (blockIdx.x >> 4) * 32;
    int tid = threadIdx.x;
    int r = tid >> 5, c = tid & 31;
#pragma unroll
    for (int p = 0; p < 4; p++)
        tile[p * 8 + r][c] = W[(size_t)(k0 + p * 8 + r) * 512 + n0 + c];
    __syncthreads();
#pragma unroll
    for (int p = 0; p < 4; p++) {
        int nr = p * 8 + r;
        float v = tile[c][nr];
        size_t o = (size_t)(n0 + nr) * 512 + k0 + c;
        g_Wt[o] = v;
        __nv_bfloat16 h = __float2bfloat16(v);
        g_Whi[o] = h;
        g_Wlo[o] = __float2bfloat16(v - __bfloat162float(h));
    }
}

// ---------------- calc_g ----------------
__global__ __launch_bounds__(256) void calc_g(const float* __restrict__ Wv) {
    int warp = blockIdx.x * 8 + (threadIdx.x >> 5);   // 512
    int lane = threadIdx.x & 31;
    const float* wt = g_Wt + (size_t)warp * 512;
    float a = 0.f;
#pragma unroll
    for (int m = 0; m < 16; m++) {
        int k = lane + 32 * m;
        a = fmaf(wt[k], Wv[k], a);
    }
#pragma unroll
    for (int o = 16; o > 0; o >>= 1) a += __shfl_xor_sync(0xffffffffu, a, o);
    if (lane == 0) g_g[warp] = a;
}

// ---------------- convert_x ----------------
__global__ __launch_bounds__(256) void convert_x(const float* __restrict__ X) {
    int gid = blockIdx.x * 256 + threadIdx.x;
    const float4* src = (const float4*)X;
    uint2* dh = (uint2*)g_Xhi;
    uint2* dl = (uint2*)g_Xlo;
#pragma unroll
    for (int r = 0; r < 2; r++) {
        int i = gid * 2 + r;
        float4 v = src[i];
        uint2 hi, lo;
        hi.x = packhl(v.x, v.y, lo.x);
        hi.y = packhl(v.z, v.w, lo.y);
        dh[i] = hi;
        dl[i] = lo;
    }
}

// ---------------- gemm_q (unchanged from R8) ----------------
#define GQ_STAGE 49152
#define GQ_AHI 0
#define GQ_ALO 16384
#define GQ_BHI 32768
#define GQ_BLO 40960
#define GQ_SMEM (2 * GQ_STAGE)

__device__ __forceinline__ void gq_load(uint32_t base,
        const __nv_bfloat16* Ah, const __nv_bfloat16* Al,
        const __nv_bfloat16* Bh, const __nv_bfloat16* Bl,
        int kc, int tid) {
#pragma unroll
    for (int q = 0; q < 4; q++) {
        int idx = q * 256 + tid;
        int row = idx >> 3, cg = idx & 7;
        uint32_t so = SW128((uint32_t)idx * 16);
        cp16(base + GQ_AHI + so, Ah + (size_t)row * 512 + kc + cg * 8);
        cp16(base + GQ_ALO + so, Al + (size_t)row * 512 + kc + cg * 8);
    }
#pragma unroll
    for (int q = 0; q < 2; q++) {
        int idx = q * 256 + tid;
        int row = idx >> 3, cg = idx & 7;
        uint32_t so = SW128((uint32_t)idx * 16);
        cp16(base + GQ_BHI + so, Bh + (size_t)row * 512 + kc + cg * 8);
        cp16(base + GQ_BLO + so, Bl + (size_t)row * 512 + kc + cg * 8);
    }
}

__global__ __launch_bounds__(256, 2) void gemm_q() {
    extern __shared__ char sm[];
    uint32_t sb = smem_u32(sm);
    int tid = threadIdx.x, lane = tid & 31, w = tid >> 5;
    int bid = blockIdx.x;
    int r0 = (bid >> 3) * 128;
    int h = bid & 7;
    int b = r0 >> 11, srow0 = r0 & 2047;
    const __nv_bfloat16* Ah = g_Xhi + (size_t)r0 * 512;
    const __nv_bfloat16* Al = g_Xlo + (size_t)r0 * 512;
    const __nv_bfloat16* Bh = g_Whi + (size_t)h * 64 * 512;
    const __nv_bfloat16* Bl = g_Wlo + (size_t)h * 64 * 512;

    int row_a = w * 16 + (lane & 15);
    uint32_t a_sw = (uint32_t)((row_a & 7) << 4);
    uint32_t a_hi16 = (uint32_t)((lane >> 4) * 16);
    int nrow_base = (lane & 7) + ((lane >> 4) << 3);
    uint32_t b_sw = (uint32_t)((lane & 7) << 4);
    uint32_t b_c16 = (uint32_t)(((lane >> 3) & 1) * 16);

    float cacc[8][4];
#pragma unroll
    for (int nb = 0; nb < 8; nb++)
#pragma unroll
        for (int r = 0; r < 4; r++) cacc[nb][r] = 0.f;

    gq_load(sb, Ah, Al, Bh, Bl, 0, tid);
    cp_commit();

    for (int i = 0; i < 8; i++) {
        int buf = i & 1;
        __syncthreads();
        if (i < 7) {
            gq_load(sb + (buf ^ 1) * GQ_STAGE, Ah, Al, Bh, Bl, (i + 1) * 64, tid);
            cp_commit();
            cp_wait<1>();
        } else {
            cp_wait<0>();
        }
        __syncthreads();
        uint32_t aHiB = sb + buf * GQ_STAGE + GQ_AHI + (uint32_t)row_a * 128;
        uint32_t aLoB = sb + buf * GQ_STAGE + GQ_ALO + (uint32_t)row_a * 128;
        uint32_t bHiB = sb + buf * GQ_STAGE + GQ_BHI;
        uint32_t bLoB = sb + buf * GQ_STAGE + GQ_BLO;
#pragma unroll
        for (int kk = 0; kk < 4; kk++) {
            uint32_t acol = ((uint32_t)(kk * 32) + a_hi16) ^ a_sw;
            uint32_t ahi[4], alo[4];
            ldsm4(ahi, aHiB + acol);
            ldsm4(alo, aLoB + acol);
            uint32_t bcol = ((uint32_t)(kk * 32) + b_c16) ^ b_sw;
#pragma unroll
            for (int nb2 = 0; nb2 < 4; nb2++) {
                uint32_t boff = (uint32_t)(nrow_base + nb2 * 16) * 128 + bcol;
                uint32_t bhi[4], blo[4];
                ldsm4(bhi, bHiB + boff);
                ldsm4(blo, bLoB + boff);
                mma16816(cacc[2 * nb2],     ahi, bhi);
                mma16816(cacc[2 * nb2],     ahi, blo);
                mma16816(cacc[2 * nb2],     alo, bhi);
                mma16816(cacc[2 * nb2 + 1], ahi, bhi + 2);
                mma16816(cacc[2 * nb2 + 1], ahi, blo + 2);
                mma16816(cacc[2 * nb2 + 1], alo, bhi + 2);
            }
        }
    }
    __syncthreads();

    // ---- norms + u = Q.g ----
    float sA = 0.f, sB = 0.f, uA = 0.f, uB = 0.f;
#pragma unroll
    for (int nb = 0; nb < 8; nb++) {
        int c0 = nb * 8 + (lane & 3) * 2;
        float2 gg = *(const float2*)&g_g[h * 64 + c0];
        sA = fmaf(cacc[nb][0], cacc[nb][0], sA);
        sA = fmaf(cacc[nb][1], cacc[nb][1], sA);
        sB = fmaf(cacc[nb][2], cacc[nb][2], sB);
        sB = fmaf(cacc[nb][3], cacc[nb][3], sB);
        uA = fmaf(cacc[nb][0], gg.x, uA);
        uA = fmaf(cacc[nb][1], gg.y, uA);
        uB = fmaf(cacc[nb][2], gg.x, uB);
        uB = fmaf(cacc[nb][3], gg.y, uB);
    }
#pragma unroll
    for (int o = 1; o <= 2; o <<= 1) {
        sA += __shfl_xor_sync(0xffffffffu, sA, o);
        sB += __shfl_xor_sync(0xffffffffu, sB, o);
        uA += __shfl_xor_sync(0xffffffffu, uA, o);
        uB += __shfl_xor_sync(0xffffffffu, uB, o);
    }
    int rA = w * 16 + (lane >> 2);
    if ((lane & 3) == 0) {
        int base = (b * 8 + h) * S_LEN + srow0;
        g_cu[base + rA]     = make_float2(-0.125f * LOG2E * sqrtf(sA), uA);
        g_cu[base + rA + 8] = make_float2(-0.125f * LOG2E * sqrtf(sB), uB);
    }

    // ---- stage Q hi/lo ----
    uint32_t* sHi32 = (uint32_t*)sm;
    uint32_t* sLo32 = (uint32_t*)(sm + 16896);
#pragma unroll
    for (int nb = 0; nb < 8; nb++) {
        int cslot = nb * 4 + (lane & 3);
        uint32_t lo0, lo1;
        uint32_t hi0 = packhl(cacc[nb][0], cacc[nb][1], lo0);
        uint32_t hi1 = packhl(cacc[nb][2], cacc[nb][3], lo1);
        sHi32[rA * 33 + cslot] = hi0;
        sLo32[rA * 33 + cslot] = lo0;
        sHi32[(rA + 8) * 33 + cslot] = hi1;
        sLo32[(rA + 8) * 33 + cslot] = lo1;
    }
    __syncthreads();
    uint32_t* dH = (uint32_t*)(g_Qhi + ((size_t)(b * 8 + h) * S_LEN + srow0) * 64);
    uint32_t* dL = (uint32_t*)(g_Qlo + ((size_t)(b * 8 + h) * S_LEN + srow0) * 64);
#pragma unroll
    for (int q = 0; q < 16; q++) {
        int linear = q * 256 + tid;
        int row = linear >> 5, c = linear & 31;
        dH[row * 32 + c] = sHi32[row * 33 + c];
        dL[row * 32 + c] = sLo32[row * 33 + c];
    }
}

// ---------------- attn_pairs: one CTA per unordered tile pair --------------
// smem: QSHI 16K | QSLO 16K | QTHI 16K | QTLO 16K | CUI 1K | CUJ 1K |
//       STG_D 4K | STG_N 4K = 75776 B
#define AP_QSHI 0
#define AP_QSLO 16384
#define AP_QTHI 32768
#define AP_QTLO 49152
#define AP_CUI  65536
#define AP_CUJ  66560
#define AP_STGD 67584
#define AP_STGN 71680
#define AP_SMEM 75776

__global__ __launch_bounds__(256, 2) void attn_pairs() {
    extern __shared__ char sm[];
    uint32_t sb = smem_u32(sm);
    int tid = threadIdx.x;
    int lane = tid & 31, w = tid >> 5;
    int bid = blockIdx.x;
    int bh = bid / 136;
    int p = bid - bh * 136;
    int i = 0;
    while (p >= 16 - i) { p -= 16 - i; i++; }
    int j = i + p;
    int bhS = bh * S_LEN;

    const __nv_bfloat16* qhiB = g_Qhi + (size_t)bhS * 64;
    const __nv_bfloat16* qloB = g_Qlo + (size_t)bhS * 64;
    const uint4* shi = (const uint4*)(qhiB + (size_t)(i * 128) * 64);
    const uint4* slo = (const uint4*)(qloB + (size_t)(i * 128) * 64);
    const uint4* thi = (const uint4*)(qhiB + (size_t)(j * 128) * 64);
    const uint4* tlo = (const uint4*)(qloB + (size_t)(j * 128) * 64);

#pragma unroll
    for (int q = 0; q < 4; q++) {
        uint32_t idx = (uint32_t)(q * 256 + tid);
        uint32_t so = SW128(idx * 16);
        cp16(sb + AP_QSHI + so, shi + idx);
        cp16(sb + AP_QSLO + so, slo + idx);
        cp16(sb + AP_QTHI + so, thi + idx);
        cp16(sb + AP_QTLO + so, tlo + idx);
    }
    if (tid < 64) {
        cp16(sb + AP_CUI + tid * 16, (const char*)(g_cu + bhS + i * 128) + tid * 16);
        cp16(sb + AP_CUJ + tid * 16, (const char*)(g_cu + bhS + j * 128) + tid * 16);
    }
    cp_commit();
    cp_wait<0>();
    __syncthreads();

    int row_a = w * 16 + (lane & 15);
    uint32_t a_sw = (uint32_t)((row_a & 7) << 4);
    uint32_t a_hi16 = (uint32_t)((lane >> 4) * 16);
    uint32_t aBaseHi = sb + AP_QSHI + (uint32_t)row_a * 128;
    uint32_t aBaseLo = sb + AP_QSLO + (uint32_t)row_a * 128;
    int nrow_base = (lane & 7) + ((lane >> 4) << 3);
    uint32_t b_sw = (uint32_t)((lane & 7) << 4);
    uint32_t b_c16 = (uint32_t)(((lane >> 3) & 1) * 16);

    float cacc[16][4];
#pragma unroll
    for (int nb = 0; nb < 16; nb++)
#pragma unroll
        for (int r = 0; r < 4; r++) cacc[nb][r] = 0.f;

#pragma unroll
    for (int kk = 0; kk < 4; kk++) {
        uint32_t acol = ((uint32_t)(kk * 32) + a_hi16) ^ a_sw;
        uint32_t ahi[4], alo[4];
        ldsm4(ahi, aBaseHi + acol);
        ldsm4(alo, aBaseLo + acol);
        uint32_t bcol = ((uint32_t)(kk * 32) + b_c16) ^ b_sw;
#pragma unroll
        for (int nb2 = 0; nb2 < 8; nb2++) {
            uint32_t boff = (uint32_t)(nrow_base + nb2 * 16) * 128 + bcol;
            uint32_t bhi[4], blo[4];
            ldsm4(bhi, sb + AP_QTHI + boff);
            ldsm4(blo, sb + AP_QTLO + boff);
            mma16816(cacc[2 * nb2],     ahi, bhi);
            mma16816(cacc[2 * nb2],     ahi, blo);
            mma16816(cacc[2 * nb2],     alo, bhi);
            mma16816(cacc[2 * nb2 + 1], ahi, bhi + 2);
            mma16816(cacc[2 * nb2 + 1], ahi, blo + 2);
            mma16816(cacc[2 * nb2 + 1], alo, bhi + 2);
        }
    }

    // ---- epilogue: symmetric weights, row sums + (if i!=j) column sums ----
    const float C1 = 0.25f * LOG2E;
    const float2* scuI = (const float2*)(sm + AP_CUI);
    const float2* scuJ = (const float2*)(sm + AP_CUJ);
    float* stgD = (float*)(sm + AP_STGD);   // [8][128]
    float* stgN = (float*)(sm + AP_STGN);
    int rA = w * 16 + (lane >> 2);
    float2 cuRA = scuI[rA];
    float2 cuRB = scuI[rA + 8];
    float cnA = cuRA.x, uAr = cuRA.y;
    float cnB = cuRB.x, uBr = cuRB.y;

    float den0 = 0.f, num0 = 0.f, den1 = 0.f, num1 = 0.f;
    bool offdiag = (i != j);

#pragma unroll
    for (int nb = 0; nb < 16; nb++) {
        int col0 = nb * 8 + (lane & 3) * 2;
        float2 cj0 = scuJ[col0];
        float2 cj1 = scuJ[col0 + 1];
        float w0 = ex2(fmaf(cacc[nb][0], C1, cnA + cj0.x));
        float w1 = ex2(fmaf(cacc[nb][1], C1, cnA + cj1.x));
        float w2 = ex2(fmaf(cacc[nb][2], C1, cnB + cj0.x));
        float w3 = ex2(fmaf(cacc[nb][3], C1, cnB + cj1.x));
        den0 += w0 + w1;
        num0 = fmaf(w0, cj0.y, fmaf(w1, cj1.y, num0));
        den1 += w2 + w3;
        num1 = fmaf(w2, cj0.y, fmaf(w3, cj1.y, num1));
        if (offdiag) {
            float pd0 = w0 + w2, pd1 = w1 + w3;
            float pn0 = fmaf(w0, uAr, w2 * uBr);
            float pn1 = fmaf(w1, uAr, w3 * uBr);
#pragma unroll
            for (int o = 4; o <= 16; o <<= 1) {
                pd0 += __shfl_xor_sync(0xffffffffu, pd0, o);
                pd1 += __shfl_xor_sync(0xffffffffu, pd1, o);
                pn0 += __shfl_xor_sync(0xffffffffu, pn0, o);
                pn1 += __shfl_xor_sync(0xffffffffu, pn1, o);
            }
            if (lane < 4) {
                stgD[w * 128 + col0] = pd0;
                stgD[w * 128 + col0 + 1] = pd1;
                stgN[w * 128 + col0] = pn0;
                stgN[w * 128 + col0 + 1] = pn1;
            }
        }
    }

    // row-side reduce & write (slot j for rows of block i)
#pragma unroll
    for (int o = 1; o <= 2; o <<= 1) {
        den0 += __shfl_xor_sync(0xffffffffu, den0, o);
        num0 += __shfl_xor_sync(0xffffffffu, num0, o);
        den1 += __shfl_xor_sync(0xffffffffu, den1, o);
        num1 += __shfl_xor_sync(0xffffffffu, num1, o);
    }
    if ((lane & 3) == 0) {
        size_t gr = ((size_t)bhS + i * 128 + rA) * 16 + j;
        g_pd[gr] = den0;
        g_pn[gr] = num0;
        g_pd[gr + 8 * 16] = den1;
        g_pn[gr + 8 * 16] = num1;
    }

    // col-side reduce & write (slot i for rows of block j)
    if (offdiag) {
        __syncthreads();
        if (tid < 128) {
            float d = 0.f, n = 0.f;
#pragma unroll
            for (int ww = 0; ww < 8; ww++) {
                d += stgD[ww * 128 + tid];
                n += stgN[ww * 128 + tid];
            }
            size_t gr = ((size_t)bhS + j * 128 + tid) * 16 + i;
            g_pd[gr] = d;
            g_pn[gr] = n;
        }
    }
}

// ---------------- attn_final: out = sigmoid(sum(num)/sum(den)) ------------
__global__ __launch_bounds__(256) void attn_final(float* __restrict__ out) {
    int r = blockIdx.x * 256 + threadIdx.x;   // 0..32767
    const float4* pd = (const float4*)(g_pd + (size_t)r * 16);
    const float4* pn = (const float4*)(g_pn + (size_t)r * 16);
    float d = 0.f, n = 0.f;
#pragma unroll
    for (int q = 0; q < 4; q++) {
        float4 vd = pd[q], vn = pn[q];
        d += (vd.x + vd.y) + (vd.z + vd.w);
        n += (vn.x + vn.y) + (vn.z + vn.w);
    }
    float z = n / d;
    out[r] = 1.0f / (1.0f + ex2(-z * LOG2E));
}

// ---------------- launch ----------------
extern "C" void kernel_launch(void* const* d_in, const int* in_sizes, int n_in,
                              void* d_out, int out_size) {
    const float *X = nullptr, *Wq = nullptr, *Wv = nullptr;
    for (int i = 0; i < n_in; i++) {
        if (in_sizes[i] == 2 * 2048 * 512)      X  = (const float*)d_in[i];
        else if (in_sizes[i] == 512 * 512)      Wq = (const float*)d_in[i];
        else if (in_sizes[i] == 512)            Wv = (const float*)d_in[i];
    }
    float* out = (float*)d_out;

    cudaFuncSetAttribute(gemm_q, cudaFuncAttributeMaxDynamicSharedMemorySize, GQ_SMEM);
    cudaFuncSetAttribute(attn_pairs, cudaFuncAttributeMaxDynamicSharedMemorySize, AP_SMEM);

    convert_w<<<256, 256>>>(Wq);
    calc_g<<<64, 256>>>(Wv);
    convert_x<<<1024, 256>>>(X);
    gemm_q<<<256, 256, GQ_SMEM>>>();
    attn_pairs<<<NBH * 136, 256, AP_SMEM>>>();
    attn_final<<<128, 256>>>(out);
}

// round 11
// speedup vs baseline: 4.5244x; 1.0197x over previous
#include <cuda_runtime.h>
#include <cuda_bf16.h>
#include <cstdint>

#define S_LEN 2048
#define D_DIM 512
#define NH 8
#define NROWS 4096   // B*S
#define NBH 16       // B*H

// ---------------- scratch (static device globals; no allocs) ----------------
__device__ float g_g[D_DIM];
__device__ float2 g_cu[NBH * S_LEN];                               // {cn, u}
__device__ __align__(128) __nv_bfloat16 g_Q1[NBH * S_LEN * 64];    // plane1 = bf16(Q)
__device__ __align__(128) __nv_bfloat16 g_Q2[NBH * S_LEN * 64];    // plane2 = bf16(hi+16*lo)
__device__ __align__(128) __nv_bfloat16 g_Xhi[NROWS * D_DIM];      // row-major
__device__ __align__(128) __nv_bfloat16 g_Xlo[NROWS * D_DIM];
__device__ __align__(128) __nv_bfloat16 g_Whi[D_DIM * D_DIM];      // [n][k]
__device__ __align__(128) __nv_bfloat16 g_Wlo[D_DIM * D_DIM];      // [n][k]
__device__ __align__(128) float g_Wt[D_DIM * D_DIM];               // [n][k] fp32
__device__ __align__(128) float g_pd[NBH * S_LEN * 16];            // den partials
__device__ __align__(128) float g_pn[NBH * S_LEN * 16];            // num partials

// ---------------- helpers ----------------
__device__ __forceinline__ float ex2(float x) {
    float r; asm("ex2.approx.ftz.f32 %0, %1;" : "=f"(r) : "f"(x)); return r;
}
__device__ __forceinline__ uint32_t smem_u32(const void* p) {
    uint32_t a;
    asm("{ .reg .u64 t; cvta.to.shared.u64 t, %1; cvt.u32.u64 %0, t; }" : "=r"(a) : "l"(p));
    return a;
}
#define LOG2E 1.4426950408889634f
#define SW128(o) ((o) ^ ((((uint32_t)(o)) >> 3) & 0x70))

__device__ __forceinline__ void ldsm4(uint32_t* r, uint32_t addr) {
    asm volatile("ldmatrix.sync.aligned.m8n8.x4.shared.b16 {%0,%1,%2,%3}, [%4];"
                 : "=r"(r[0]), "=r"(r[1]), "=r"(r[2]), "=r"(r[3]) : "r"(addr));
}
__device__ __forceinline__ void mma16816(float* c, const uint32_t* a, const uint32_t* b) {
    asm volatile("mma.sync.aligned.m16n8k16.row.col.f32.bf16.bf16.f32 "
                 "{%0,%1,%2,%3}, {%4,%5,%6,%7}, {%8,%9}, {%0,%1,%2,%3};"
                 : "+f"(c[0]), "+f"(c[1]), "+f"(c[2]), "+f"(c[3])
                 : "r"(a[0]), "r"(a[1]), "r"(a[2]), "r"(a[3]), "r"(b[0]), "r"(b[1]));
}
__device__ __forceinline__ void cp16(uint32_t dst, const void* src) {
    asm volatile("cp.async.cg.shared.global [%0], [%1], 16;" :: "r"(dst), "l"(src));
}
__device__ __forceinline__ void cp_commit() {
    asm volatile("cp.async.commit_group;" ::: "memory");
}
template <int N>
__device__ __forceinline__ void cp_wait() {
    asm volatile("cp.async.wait_group %0;" :: "n"(N) : "memory");
}
// hi/lo split (for X, W operands of gemm_q)
__device__ __forceinline__ uint32_t packhl(float a, float b, uint32_t& lo) {
    __nv_bfloat16 h0 = __float2bfloat16(a);
    __nv_bfloat16 h1 = __float2bfloat16(b);
    __nv_bfloat162 hh; hh.x = h0; hh.y = h1;
    __nv_bfloat162 ll;
    ll.x = __float2bfloat16(a - __bfloat162float(h0));
    ll.y = __float2bfloat16(b - __bfloat162float(h1));
    lo = *(uint32_t*)&ll;
    return *(uint32_t*)&hh;
}
// two-plane split for symmetric Gram: plane1 = bf16(q), plane2 = bf16(hi + 16*lo)
__device__ __forceinline__ uint32_t packp(float a, float b, uint32_t& p2) {
    __nv_bfloat16 h0 = __float2bfloat16(a);
    __nv_bfloat16 h1 = __float2bfloat16(b);
    float f0 = __bfloat162float(h0), f1 = __bfloat162float(h1);
    __nv_bfloat162 hh; hh.x = h0; hh.y = h1;
    __nv_bfloat162 pp;
    pp.x = __float2bfloat16(fmaf(16.f, a - f0, f0));
    pp.y = __float2bfloat16(fmaf(16.f, b - f1, f1));
    p2 = *(uint32_t*)&pp;
    return *(uint32_t*)&hh;
}

// ---------------- convert_w: W[k][n] -> Wt/Whi/Wlo [n][k] ----------------
__global__ __launch_bounds__(256) void convert_w(const float* __restrict__ W) {
    __shared__ float tile[32][33];
    int k0 = (blockIdx.x & 15) * 32;
    int n0 = (blockIdx.x >> 4) * 32;
    int tid = threadIdx.x;
    int r = tid >> 5, c = tid & 31;
#pragma unroll
    for (int p = 0; p < 4; p++)
        tile[p * 8 + r][c] = W[(size_t)(k0 + p * 8 + r) * 512 + n0 + c];
    __syncthreads();
#pragma unroll
    for (int p = 0; p < 4; p++) {
        int nr = p * 8 + r;
        float v = tile[c][nr];
        size_t o = (size_t)(n0 + nr) * 512 + k0 + c;
        g_Wt[o] = v;
        __nv_bfloat16 h = __float2bfloat16(v);
        g_Whi[o] = h;
        g_Wlo[o] = __float2bfloat16(v - __bfloat162float(h));
    }
}

// ---------------- calc_g ----------------
__global__ __launch_bounds__(256) void calc_g(const float* __restrict__ Wv) {
    int warp = blockIdx.x * 8 + (threadIdx.x >> 5);   // 512
    int lane = threadIdx.x & 31;
    const float* wt = g_Wt + (size_t)warp * 512;
    float a = 0.f;
#pragma unroll
    for (int m = 0; m < 16; m++) {
        int k = lane + 32 * m;
        a = fmaf(wt[k], Wv[k], a);
    }
#pragma unroll
    for (int o = 16; o > 0; o >>= 1) a += __shfl_xor_sync(0xffffffffu, a, o);
    if (lane == 0) g_g[warp] = a;
}

// ---------------- convert_x ----------------
__global__ __launch_bounds__(256) void convert_x(const float* __restrict__ X) {
    int gid = blockIdx.x * 256 + threadIdx.x;
    const float4* src = (const float4*)X;
    uint2* dh = (uint2*)g_Xhi;
    uint2* dl = (uint2*)g_Xlo;
#pragma unroll
    for (int r = 0; r < 2; r++) {
        int i = gid * 2 + r;
        float4 v = src[i];
        uint2 hi, lo;
        hi.x = packhl(v.x, v.y, lo.x);
        hi.y = packhl(v.z, v.w, lo.y);
        dh[i] = hi;
        dl[i] = lo;
    }
}

// ---------------- gemm_q: Q = X@W (3-pass exact), emit planes + norms + u --
#define GQ_STAGE 49152
#define GQ_AHI 0
#define GQ_ALO 16384
#define GQ_BHI 32768
#define GQ_BLO 40960
#define GQ_SMEM (2 * GQ_STAGE)

__device__ __forceinline__ void gq_load(uint32_t base,
        const __nv_bfloat16* Ah, const __nv_bfloat16* Al,
        const __nv_bfloat16* Bh, const __nv_bfloat16* Bl,
        int kc, int tid) {
#pragma unroll
    for (int q = 0; q < 4; q++) {
        int idx = q * 256 + tid;
        int row = idx >> 3, cg = idx & 7;
        uint32_t so = SW128((uint32_t)idx * 16);
        cp16(base + GQ_AHI + so, Ah + (size_t)row * 512 + kc + cg * 8);
        cp16(base + GQ_ALO + so, Al + (size_t)row * 512 + kc + cg * 8);
    }
#pragma unroll
    for (int q = 0; q < 2; q++) {
        int idx = q * 256 + tid;
        int row = idx >> 3, cg = idx & 7;
        uint32_t so = SW128((uint32_t)idx * 16);
        cp16(base + GQ_BHI + so, Bh + (size_t)row * 512 + kc + cg * 8);
        cp16(base + GQ_BLO + so, Bl + (size_t)row * 512 + kc + cg * 8);
    }
}

__global__ __launch_bounds__(256, 2) void gemm_q() {
    extern __shared__ char sm[];
    uint32_t sb = smem_u32(sm);
    int tid = threadIdx.x, lane = tid & 31, w = tid >> 5;
    int bid = blockIdx.x;
    int r0 = (bid >> 3) * 128;
    int h = bid & 7;
    int b = r0 >> 11, srow0 = r0 & 2047;
    const __nv_bfloat16* Ah = g_Xhi + (size_t)r0 * 512;
    const __nv_bfloat16* Al = g_Xlo + (size_t)r0 * 512;
    const __nv_bfloat16* Bh = g_Whi + (size_t)h * 64 * 512;
    const __nv_bfloat16* Bl = g_Wlo + (size_t)h * 64 * 512;

    int row_a = w * 16 + (lane & 15);
    uint32_t a_sw = (uint32_t)((row_a & 7) << 4);
    uint32_t a_hi16 = (uint32_t)((lane >> 4) * 16);
    int nrow_base = (lane & 7) + ((lane >> 4) << 3);
    uint32_t b_sw = (uint32_t)((lane & 7) << 4);
    uint32_t b_c16 = (uint32_t)(((lane >> 3) & 1) * 16);

    float cacc[8][4];
#pragma unroll
    for (int nb = 0; nb < 8; nb++)
#pragma unroll
        for (int r = 0; r < 4; r++) cacc[nb][r] = 0.f;

    gq_load(sb, Ah, Al, Bh, Bl, 0, tid);
    cp_commit();

    for (int i = 0; i < 8; i++) {
        int buf = i & 1;
        __syncthreads();
        if (i < 7) {
            gq_load(sb + (buf ^ 1) * GQ_STAGE, Ah, Al, Bh, Bl, (i + 1) * 64, tid);
            cp_commit();
            cp_wait<1>();
        } else {
            cp_wait<0>();
        }
        __syncthreads();
        uint32_t aHiB = sb + buf * GQ_STAGE + GQ_AHI + (uint32_t)row_a * 128;
        uint32_t aLoB = sb + buf * GQ_STAGE + GQ_ALO + (uint32_t)row_a * 128;
        uint32_t bHiB = sb + buf * GQ_STAGE + GQ_BHI;
        uint32_t bLoB = sb + buf * GQ_STAGE + GQ_BLO;
#pragma unroll
        for (int kk = 0; kk < 4; kk++) {
            uint32_t acol = ((uint32_t)(kk * 32) + a_hi16) ^ a_sw;
            uint32_t ahi[4], alo[4];
            ldsm4(ahi, aHiB + acol);
            ldsm4(alo, aLoB + acol);
            uint32_t bcol = ((uint32_t)(kk * 32) + b_c16) ^ b_sw;
#pragma unroll
            for (int nb2 = 0; nb2 < 4; nb2++) {
                uint32_t boff = (uint32_t)(nrow_base + nb2 * 16) * 128 + bcol;
                uint32_t bhi[4], blo[4];
                ldsm4(bhi, bHiB + boff);
                ldsm4(blo, bLoB + boff);
                mma16816(cacc[2 * nb2],     ahi, bhi);
                mma16816(cacc[2 * nb2],     ahi, blo);
                mma16816(cacc[2 * nb2],     alo, bhi);
                mma16816(cacc[2 * nb2 + 1], ahi, bhi + 2);
                mma16816(cacc[2 * nb2 + 1], ahi, blo + 2);
                mma16816(cacc[2 * nb2 + 1], alo, bhi + 2);
            }
        }
    }
    __syncthreads();

    // ---- norms + u = Q.g ----
    float sA = 0.f, sB = 0.f, uA = 0.f, uB = 0.f;
#pragma unroll
    for (int nb = 0; nb < 8; nb++) {
        int c0 = nb * 8 + (lane & 3) * 2;
        float2 gg = *(const float2*)&g_g[h * 64 + c0];
        sA = fmaf(cacc[nb][0], cacc[nb][0], sA);
        sA = fmaf(cacc[nb][1], cacc[nb][1], sA);
        sB = fmaf(cacc[nb][2], cacc[nb][2], sB);
        sB = fmaf(cacc[nb][3], cacc[nb][3], sB);
        uA = fmaf(cacc[nb][0], gg.x, uA);
        uA = fmaf(cacc[nb][1], gg.y, uA);
        uB = fmaf(cacc[nb][2], gg.x, uB);
        uB = fmaf(cacc[nb][3], gg.y, uB);
    }
#pragma unroll
    for (int o = 1; o <= 2; o <<= 1) {
        sA += __shfl_xor_sync(0xffffffffu, sA, o);
        sB += __shfl_xor_sync(0xffffffffu, sB, o);
        uA += __shfl_xor_sync(0xffffffffu, uA, o);
        uB += __shfl_xor_sync(0xffffffffu, uB, o);
    }
    int rA = w * 16 + (lane >> 2);
    if ((lane & 3) == 0) {
        int base = (b * 8 + h) * S_LEN + srow0;
        g_cu[base + rA]     = make_float2(-0.125f * LOG2E * sqrtf(sA), uA);
        g_cu[base + rA + 8] = make_float2(-0.125f * LOG2E * sqrtf(sB), uB);
    }

    // ---- stage Q planes (padded [128][33] u32) ----
    uint32_t* s1 = (uint32_t*)sm;
    uint32_t* s2 = (uint32_t*)(sm + 16896);
#pragma unroll
    for (int nb = 0; nb < 8; nb++) {
        int cslot = nb * 4 + (lane & 3);
        uint32_t p0, p1;
        uint32_t h0 = packp(cacc[nb][0], cacc[nb][1], p0);
        uint32_t h1 = packp(cacc[nb][2], cacc[nb][3], p1);
        s1[rA * 33 + cslot] = h0;
        s2[rA * 33 + cslot] = p0;
        s1[(rA + 8) * 33 + cslot] = h1;
        s2[(rA + 8) * 33 + cslot] = p1;
    }
    __syncthreads();
    uint32_t* d1 = (uint32_t*)(g_Q1 + ((size_t)(b * 8 + h) * S_LEN + srow0) * 64);
    uint32_t* d2 = (uint32_t*)(g_Q2 + ((size_t)(b * 8 + h) * S_LEN + srow0) * 64);
#pragma unroll
    for (int q = 0; q < 16; q++) {
        int linear = q * 256 + tid;
        int row = linear >> 5, c = linear & 31;
        d1[row * 32 + c] = s1[row * 33 + c];
        d2[row * 32 + c] = s2[row * 33 + c];
    }
}

// ---------------- attn_pairs: pairs + 2-plane Gram (128 mma/warp) ---------
// smem: QS1 16K | QS2 16K | QT1 16K | QT2 16K | CUI 1K | CUJ 1K |
//       STG_D 4K | STG_N 4K = 75776 B
#define AP_QS1 0
#define AP_QS2 16384
#define AP_QT1 32768
#define AP_QT2 49152
#define AP_CUI  65536
#define AP_CUJ  66560
#define AP_STGD 67584
#define AP_STGN 71680
#define AP_SMEM 75776

__global__ __launch_bounds__(256, 2) void attn_pairs() {
    extern __shared__ char sm[];
    uint32_t sb = smem_u32(sm);
    int tid = threadIdx.x;
    int lane = tid & 31, w = tid >> 5;
    int bid = blockIdx.x;
    int bh = bid / 136;
    int p = bid - bh * 136;
    int i = 0;
    while (p >= 16 - i) { p -= 16 - i; i++; }
    int j = i + p;
    int bhS = bh * S_LEN;

    const __nv_bfloat16* q1B = g_Q1 + (size_t)bhS * 64;
    const __nv_bfloat16* q2B = g_Q2 + (size_t)bhS * 64;
    const uint4* s1g = (const uint4*)(q1B + (size_t)(i * 128) * 64);
    const uint4* s2g = (const uint4*)(q2B + (size_t)(i * 128) * 64);
    const uint4* t1g = (const uint4*)(q1B + (size_t)(j * 128) * 64);
    const uint4* t2g = (const uint4*)(q2B + (size_t)(j * 128) * 64);

#pragma unroll
    for (int q = 0; q < 4; q++) {
        uint32_t idx = (uint32_t)(q * 256 + tid);
        uint32_t so = SW128(idx * 16);
        cp16(sb + AP_QS1 + so, s1g + idx);
        cp16(sb + AP_QS2 + so, s2g + idx);
        cp16(sb + AP_QT1 + so, t1g + idx);
        cp16(sb + AP_QT2 + so, t2g + idx);
    }
    if (tid < 64) {
        cp16(sb + AP_CUI + tid * 16, (const char*)(g_cu + bhS + i * 128) + tid * 16);
        cp16(sb + AP_CUJ + tid * 16, (const char*)(g_cu + bhS + j * 128) + tid * 16);
    }
    cp_commit();
    cp_wait<0>();
    __syncthreads();

    int row_a = w * 16 + (lane & 15);
    uint32_t a_sw = (uint32_t)((row_a & 7) << 4);
    uint32_t a_hi16 = (uint32_t)((lane >> 4) * 16);
    int nrow_base = (lane & 7) + ((lane >> 4) << 3);
    uint32_t b_sw = (uint32_t)((lane & 7) << 4);
    uint32_t b_c16 = (uint32_t)(((lane >> 3) & 1) * 16);

    // A fragments resident: 4 kk-chunks x 2 planes
    uint32_t a1[4][4], a2[4][4];
    uint32_t aB1 = sb + AP_QS1 + (uint32_t)row_a * 128;
    uint32_t aB2 = sb + AP_QS2 + (uint32_t)row_a * 128;
#pragma unroll
    for (int kk = 0; kk < 4; kk++) {
        uint32_t acol = ((uint32_t)(kk * 32) + a_hi16) ^ a_sw;
        ldsm4(a1[kk], aB1 + acol);
        ldsm4(a2[kk], aB2 + acol);
    }

    const float C1 = 0.25f * LOG2E;
    const float CA = C1 * (15.0f / 16.0f);
    const float CB = C1 * (1.0f / 16.0f);
    const float2* scuI = (const float2*)(sm + AP_CUI);
    const float2* scuJ = (const float2*)(sm + AP_CUJ);
    float* stgD = (float*)(sm + AP_STGD);   // [8][128]
    float* stgN = (float*)(sm + AP_STGN);
    int rA = w * 16 + (lane >> 2);
    float2 cuRA = scuI[rA];
    float2 cuRB = scuI[rA + 8];
    float cnA = cuRA.x, uAr = cuRA.y;
    float cnB = cuRB.x, uBr = cuRB.y;

    float den0 = 0.f, num0 = 0.f, den1 = 0.f, num1 = 0.f;
    bool offdiag = (i != j);

#pragma unroll
    for (int nb2 = 0; nb2 < 8; nb2++) {
        uint32_t nrow = (uint32_t)(nrow_base + nb2 * 16);
        float c1[2][4], c2[2][4];
#pragma unroll
        for (int nblk = 0; nblk < 2; nblk++)
#pragma unroll
            for (int r = 0; r < 4; r++) { c1[nblk][r] = 0.f; c2[nblk][r] = 0.f; }

#pragma unroll
        for (int kk = 0; kk < 4; kk++) {
            uint32_t boff = nrow * 128 + (((uint32_t)(kk * 32) + b_c16) ^ b_sw);
            uint32_t b1[4], b2[4];
            ldsm4(b1, sb + AP_QT1 + boff);
            ldsm4(b2, sb + AP_QT2 + boff);
            mma16816(c1[0], a1[kk], b1);
            mma16816(c1[1], a1[kk], b1 + 2);
            mma16816(c2[0], a2[kk], b2);
            mma16816(c2[1], a2[kk], b2 + 2);
        }

#pragma unroll
        for (int nblk = 0; nblk < 2; nblk++) {
            int nb = 2 * nb2 + nblk;
            int col0 = nb * 8 + (lane & 3) * 2;
            float2 cj0 = scuJ[col0];
            float2 cj1 = scuJ[col0 + 1];
            float w0 = ex2(fmaf(c1[nblk][0], CA, fmaf(c2[nblk][0], CB, cnA + cj0.x)));
            float w1 = ex2(fmaf(c1[nblk][1], CA, fmaf(c2[nblk][1], CB, cnA + cj1.x)));
            float w2 = ex2(fmaf(c1[nblk][2], CA, fmaf(c2[nblk][2], CB, cnB + cj0.x)));
            float w3 = ex2(fmaf(c1[nblk][3], CA, fmaf(c2[nblk][3], CB, cnB + cj1.x)));
            den0 += w0 + w1;
            num0 = fmaf(w0, cj0.y, fmaf(w1, cj1.y, num0));
            den1 += w2 + w3;
            num1 = fmaf(w2, cj0.y, fmaf(w3, cj1.y, num1));
            if (offdiag) {
                float pd0 = w0 + w2, pd1 = w1 + w3;
                float pn0 = fmaf(w0, uAr, w2 * uBr);
                float pn1 = fmaf(w1, uAr, w3 * uBr);
#pragma unroll
                for (int o = 4; o <= 16; o <<= 1) {
                    pd0 += __shfl_xor_sync(0xffffffffu, pd0, o);
                    pd1 += __shfl_xor_sync(0xffffffffu, pd1, o);
                    pn0 += __shfl_xor_sync(0xffffffffu, pn0, o);
                    pn1 += __shfl_xor_sync(0xffffffffu, pn1, o);
                }
                if (lane < 4) {
                    stgD[w * 128 + col0] = pd0;
                    stgD[w * 128 + col0 + 1] = pd1;
                    stgN[w * 128 + col0] = pn0;
                    stgN[w * 128 + col0 + 1] = pn1;
                }
            }
        }
    }

    // row-side reduce & write (slot j for rows of block i)
#pragma unroll
    for (int o = 1; o <= 2; o <<= 1) {
        den0 += __shfl_xor_sync(0xffffffffu, den0, o);
        num0 += __shfl_xor_sync(0xffffffffu, num0, o);
        den1 += __shfl_xor_sync(0xffffffffu, den1, o);
        num1 += __shfl_xor_sync(0xffffffffu, num1, o);
    }
    if ((lane & 3) == 0) {
        size_t gr = ((size_t)bhS + i * 128 + rA) * 16 + j;
        g_pd[gr] = den0;
        g_pn[gr] = num0;
        g_pd[gr + 8 * 16] = den1;
        g_pn[gr + 8 * 16] = num1;
    }

    // col-side reduce & write (slot i for rows of block j)
    if (offdiag) {
        __syncthreads();
        if (tid < 128) {
            float d = 0.f, n = 0.f;
#pragma unroll
            for (int ww = 0; ww < 8; ww++) {
                d += stgD[ww * 128 + tid];
                n += stgN[ww * 128 + tid];
            }
            size_t gr = ((size_t)bhS + j * 128 + tid) * 16 + i;
            g_pd[gr] = d;
            g_pn[gr] = n;
        }
    }
}

// ---------------- attn_final: out = sigmoid(sum(num)/sum(den)) ------------
__global__ __launch_bounds__(256) void attn_final(float* __restrict__ out) {
    int r = blockIdx.x * 256 + threadIdx.x;   // 0..32767
    const float4* pd = (const float4*)(g_pd + (size_t)r * 16);
    const float4* pn = (const float4*)(g_pn + (size_t)r * 16);
    float d = 0.f, n = 0.f;
#pragma unroll
    for (int q = 0; q < 4; q++) {
        float4 vd = pd[q], vn = pn[q];
        d += (vd.x + vd.y) + (vd.z + vd.w);
        n += (vn.x + vn.y) + (vn.z + vn.w);
    }
    float z = n / d;
    out[r] = 1.0f / (1.0f + ex2(-z * LOG2E));
}

// ---------------- launch ----------------
extern "C" void kernel_launch(void* const* d_in, const int* in_sizes, int n_in,
                              void* d_out, int out_size) {
    const float *X = nullptr, *Wq = nullptr, *Wv = nullptr;
    for (int i = 0; i < n_in; i++) {
        if (in_sizes[i] == 2 * 2048 * 512)      X  = (const float*)d_in[i];
        else if (in_sizes[i] == 512 * 512)      Wq = (const float*)d_in[i];
        else if (in_sizes[i] == 512)            Wv = (const float*)d_in[i];
    }
    float* out = (float*)d_out;

    cudaFuncSetAttribute(gemm_q, cudaFuncAttributeMaxDynamicSharedMemorySize, GQ_SMEM);
    cudaFuncSetAttribute(attn_pairs, cudaFuncAttributeMaxDynamicSharedMemorySize, AP_SMEM);

    convert_w<<<256, 256>>>(Wq);
    calc_g<<<64, 256>>>(Wv);
    convert_x<<<1024, 256>>>(X);
    gemm_q<<<256, 256, GQ_SMEM>>>();
    attn_pairs<<<NBH * 136, 256, AP_SMEM>>>();
    attn_final<<<128, 256>>>(out);
}

// round 12
// speedup vs baseline: 4.7551x; 1.0510x over previous
#include <cuda_runtime.h>
#include <cuda_bf16.h>
#include <cstdint>

#define S_LEN 2048
#define D_DIM 512
#define NH 8
#define NROWS 4096   // B*S
#define NBH 16       // B*H

// ---------------- scratch (static device globals; no allocs) ----------------
__device__ float g_g[D_DIM];
__device__ float2 g_cu[NBH * S_LEN];                               // {cn, u}
__device__ __align__(128) __nv_bfloat16 g_Q1[NBH * S_LEN * 64];    // plane1 = bf16(Q)
__device__ __align__(128) __nv_bfloat16 g_Q2[NBH * S_LEN * 64];    // plane2 = bf16(hi+16*lo)
__device__ __align__(128) __nv_bfloat16 g_Xhi[NROWS * D_DIM];      // row-major
__device__ __align__(128) __nv_bfloat16 g_Xlo[NROWS * D_DIM];
__device__ __align__(128) __nv_bfloat16 g_Whi[D_DIM * D_DIM];      // [n][k]
__device__ __align__(128) __nv_bfloat16 g_Wlo[D_DIM * D_DIM];      // [n][k]
__device__ __align__(128) float g_Wt[D_DIM * D_DIM];               // [n][k] fp32
__device__ __align__(128) float g_pd[NBH * S_LEN * 16];            // den partials
__device__ __align__(128) float g_pn[NBH * S_LEN * 16];            // num partials

// ---------------- helpers ----------------
__device__ __forceinline__ float ex2(float x) {
    float r; asm("ex2.approx.ftz.f32 %0, %1;" : "=f"(r) : "f"(x)); return r;
}
__device__ __forceinline__ uint32_t smem_u32(const void* p) {
    uint32_t a;
    asm("{ .reg .u64 t; cvta.to.shared.u64 t, %1; cvt.u32.u64 %0, t; }" : "=r"(a) : "l"(p));
    return a;
}
#define LOG2E 1.4426950408889634f
#define SW128(o) ((o) ^ ((((uint32_t)(o)) >> 3) & 0x70))

__device__ __forceinline__ void ldsm4(uint32_t* r, uint32_t addr) {
    asm volatile("ldmatrix.sync.aligned.m8n8.x4.shared.b16 {%0,%1,%2,%3}, [%4];"
                 : "=r"(r[0]), "=r"(r[1]), "=r"(r[2]), "=r"(r[3]) : "r"(addr));
}
__device__ __forceinline__ void mma16816(float* c, const uint32_t* a, const uint32_t* b) {
    asm volatile("mma.sync.aligned.m16n8k16.row.col.f32.bf16.bf16.f32 "
                 "{%0,%1,%2,%3}, {%4,%5,%6,%7}, {%8,%9}, {%0,%1,%2,%3};"
                 : "+f"(c[0]), "+f"(c[1]), "+f"(c[2]), "+f"(c[3])
                 : "r"(a[0]), "r"(a[1]), "r"(a[2]), "r"(a[3]), "r"(b[0]), "r"(b[1]));
}
__device__ __forceinline__ void cp16(uint32_t dst, const void* src) {
    asm volatile("cp.async.cg.shared.global [%0], [%1], 16;" :: "r"(dst), "l"(src));
}
__device__ __forceinline__ void cp_commit() {
    asm volatile("cp.async.commit_group;" ::: "memory");
}
template <int N>
__device__ __forceinline__ void cp_wait() {
    asm volatile("cp.async.wait_group %0;" :: "n"(N) : "memory");
}
// hi/lo split (for X, W operands of gemm_q)
__device__ __forceinline__ uint32_t packhl(float a, float b, uint32_t& lo) {
    __nv_bfloat16 h0 = __float2bfloat16(a);
    __nv_bfloat16 h1 = __float2bfloat16(b);
    __nv_bfloat162 hh; hh.x = h0; hh.y = h1;
    __nv_bfloat162 ll;
    ll.x = __float2bfloat16(a - __bfloat162float(h0));
    ll.y = __float2bfloat16(b - __bfloat162float(h1));
    lo = *(uint32_t*)&ll;
    return *(uint32_t*)&hh;
}
// two-plane split for symmetric Gram: plane1 = bf16(q), plane2 = bf16(hi + 16*lo)
__device__ __forceinline__ uint32_t packp(float a, float b, uint32_t& p2) {
    __nv_bfloat16 h0 = __float2bfloat16(a);
    __nv_bfloat16 h1 = __float2bfloat16(b);
    float f0 = __bfloat162float(h0), f1 = __bfloat162float(h1);
    __nv_bfloat162 hh; hh.x = h0; hh.y = h1;
    __nv_bfloat162 pp;
    pp.x = __float2bfloat16(fmaf(16.f, a - f0, f0));
    pp.y = __float2bfloat16(fmaf(16.f, b - f1, f1));
    p2 = *(uint32_t*)&pp;
    return *(uint32_t*)&hh;
}

// ---------------- convert_w: W[k][n] -> Wt/Whi/Wlo [n][k] ----------------
__global__ __launch_bounds__(256) void convert_w(const float* __restrict__ W) {
    __shared__ float tile[32][33];
    int k0 = (blockIdx.x & 15) * 32;
    int n0 = (blockIdx.x >> 4) * 32;
    int tid = threadIdx.x;
    int r = tid >> 5, c = tid & 31;
#pragma unroll
    for (int p = 0; p < 4; p++)
        tile[p * 8 + r][c] = W[(size_t)(k0 + p * 8 + r) * 512 + n0 + c];
    __syncthreads();
#pragma unroll
    for (int p = 0; p < 4; p++) {
        int nr = p * 8 + r;
        float v = tile[c][nr];
        size_t o = (size_t)(n0 + nr) * 512 + k0 + c;
        g_Wt[o] = v;
        __nv_bfloat16 h = __float2bfloat16(v);
        g_Whi[o] = h;
        g_Wlo[o] = __float2bfloat16(v - __bfloat162float(h));
    }
}

// ---------------- calc_g ----------------
__global__ __launch_bounds__(256) void calc_g(const float* __restrict__ Wv) {
    int warp = blockIdx.x * 8 + (threadIdx.x >> 5);   // 512
    int lane = threadIdx.x & 31;
    const float* wt = g_Wt + (size_t)warp * 512;
    float a = 0.f;
#pragma unroll
    for (int m = 0; m < 16; m++) {
        int k = lane + 32 * m;
        a = fmaf(wt[k], Wv[k], a);
    }
#pragma unroll
    for (int o = 16; o > 0; o >>= 1) a += __shfl_xor_sync(0xffffffffu, a, o);
    if (lane == 0) g_g[warp] = a;
}

// ---------------- convert_x ----------------
__global__ __launch_bounds__(256) void convert_x(const float* __restrict__ X) {
    int gid = blockIdx.x * 256 + threadIdx.x;
    const float4* src = (const float4*)X;
    uint2* dh = (uint2*)g_Xhi;
    uint2* dl = (uint2*)g_Xlo;
#pragma unroll
    for (int r = 0; r < 2; r++) {
        int i = gid * 2 + r;
        float4 v = src[i];
        uint2 hi, lo;
        hi.x = packhl(v.x, v.y, lo.x);
        hi.y = packhl(v.z, v.w, lo.y);
        dh[i] = hi;
        dl[i] = lo;
    }
}

// ---------------- gemm_q: Q = X@W (3-pass exact), emit planes + norms + u --
#define GQ_STAGE 49152
#define GQ_AHI 0
#define GQ_ALO 16384
#define GQ_BHI 32768
#define GQ_BLO 40960
#define GQ_SMEM (2 * GQ_STAGE)

__device__ __forceinline__ void gq_load(uint32_t base,
        const __nv_bfloat16* Ah, const __nv_bfloat16* Al,
        const __nv_bfloat16* Bh, const __nv_bfloat16* Bl,
        int kc, int tid) {
#pragma unroll
    for (int q = 0; q < 4; q++) {
        int idx = q * 256 + tid;
        int row = idx >> 3, cg = idx & 7;
        uint32_t so = SW128((uint32_t)idx * 16);
        cp16(base + GQ_AHI + so, Ah + (size_t)row * 512 + kc + cg * 8);
        cp16(base + GQ_ALO + so, Al + (size_t)row * 512 + kc + cg * 8);
    }
#pragma unroll
    for (int q = 0; q < 2; q++) {
        int idx = q * 256 + tid;
        int row = idx >> 3, cg = idx & 7;
        uint32_t so = SW128((uint32_t)idx * 16);
        cp16(base + GQ_BHI + so, Bh + (size_t)row * 512 + kc + cg * 8);
        cp16(base + GQ_BLO + so, Bl + (size_t)row * 512 + kc + cg * 8);
    }
}

__global__ __launch_bounds__(256, 2) void gemm_q() {
    extern __shared__ char sm[];
    uint32_t sb = smem_u32(sm);
    int tid = threadIdx.x, lane = tid & 31, w = tid >> 5;
    int bid = blockIdx.x;
    int r0 = (bid >> 3) * 128;
    int h = bid & 7;
    int b = r0 >> 11, srow0 = r0 & 2047;
    const __nv_bfloat16* Ah = g_Xhi + (size_t)r0 * 512;
    const __nv_bfloat16* Al = g_Xlo + (size_t)r0 * 512;
    const __nv_bfloat16* Bh = g_Whi + (size_t)h * 64 * 512;
    const __nv_bfloat16* Bl = g_Wlo + (size_t)h * 64 * 512;

    int row_a = w * 16 + (lane & 15);
    uint32_t a_sw = (uint32_t)((row_a & 7) << 4);
    uint32_t a_hi16 = (uint32_t)((lane >> 4) * 16);
    int nrow_base = (lane & 7) + ((lane >> 4) << 3);
    uint32_t b_sw = (uint32_t)((lane & 7) << 4);
    uint32_t b_c16 = (uint32_t)(((lane >> 3) & 1) * 16);

    float cacc[8][4];
#pragma unroll
    for (int nb = 0; nb < 8; nb++)
#pragma unroll
        for (int r = 0; r < 4; r++) cacc[nb][r] = 0.f;

    gq_load(sb, Ah, Al, Bh, Bl, 0, tid);
    cp_commit();

    for (int i = 0; i < 8; i++) {
        int buf = i & 1;
        __syncthreads();
        if (i < 7) {
            gq_load(sb + (buf ^ 1) * GQ_STAGE, Ah, Al, Bh, Bl, (i + 1) * 64, tid);
            cp_commit();
            cp_wait<1>();
        } else {
            cp_wait<0>();
        }
        __syncthreads();
        uint32_t aHiB = sb + buf * GQ_STAGE + GQ_AHI + (uint32_t)row_a * 128;
        uint32_t aLoB = sb + buf * GQ_STAGE + GQ_ALO + (uint32_t)row_a * 128;
        uint32_t bHiB = sb + buf * GQ_STAGE + GQ_BHI;
        uint32_t bLoB = sb + buf * GQ_STAGE + GQ_BLO;
#pragma unroll
        for (int kk = 0; kk < 4; kk++) {
            uint32_t acol = ((uint32_t)(kk * 32) + a_hi16) ^ a_sw;
            uint32_t ahi[4], alo[4];
            ldsm4(ahi, aHiB + acol);
            ldsm4(alo, aLoB + acol);
            uint32_t bcol = ((uint32_t)(kk * 32) + b_c16) ^ b_sw;
#pragma unroll
            for (int nb2 = 0; nb2 < 4; nb2++) {
                uint32_t boff = (uint32_t)(nrow_base + nb2 * 16) * 128 + bcol;
                uint32_t bhi[4], blo[4];
                ldsm4(bhi, bHiB + boff);
                ldsm4(blo, bLoB + boff);
                mma16816(cacc[2 * nb2],     ahi, bhi);
                mma16816(cacc[2 * nb2],     ahi, blo);
                mma16816(cacc[2 * nb2],     alo, bhi);
                mma16816(cacc[2 * nb2 + 1], ahi, bhi + 2);
                mma16816(cacc[2 * nb2 + 1], ahi, blo + 2);
                mma16816(cacc[2 * nb2 + 1], alo, bhi + 2);
            }
        }
    }
    __syncthreads();

    // ---- norms + u = Q.g ----
    float sA = 0.f, sB = 0.f, uA = 0.f, uB = 0.f;
#pragma unroll
    for (int nb = 0; nb < 8; nb++) {
        int c0 = nb * 8 + (lane & 3) * 2;
        float2 gg = *(const float2*)&g_g[h * 64 + c0];
        sA = fmaf(cacc[nb][0], cacc[nb][0], sA);
        sA = fmaf(cacc[nb][1], cacc[nb][1], sA);
        sB = fmaf(cacc[nb][2], cacc[nb][2], sB);
        sB = fmaf(cacc[nb][3], cacc[nb][3], sB);
        uA = fmaf(cacc[nb][0], gg.x, uA);
        uA = fmaf(cacc[nb][1], gg.y, uA);
        uB = fmaf(cacc[nb][2], gg.x, uB);
        uB = fmaf(cacc[nb][3], gg.y, uB);
    }
#pragma unroll
    for (int o = 1; o <= 2; o <<= 1) {
        sA += __shfl_xor_sync(0xffffffffu, sA, o);
        sB += __shfl_xor_sync(0xffffffffu, sB, o);
        uA += __shfl_xor_sync(0xffffffffu, uA, o);
        uB += __shfl_xor_sync(0xffffffffu, uB, o);
    }
    int rA = w * 16 + (lane >> 2);
    if ((lane & 3) == 0) {
        int base = (b * 8 + h) * S_LEN + srow0;
        g_cu[base + rA]     = make_float2(-0.125f * LOG2E * sqrtf(sA), uA);
        g_cu[base + rA + 8] = make_float2(-0.125f * LOG2E * sqrtf(sB), uB);
    }

    // ---- stage Q planes (padded [128][33] u32) ----
    uint32_t* s1 = (uint32_t*)sm;
    uint32_t* s2 = (uint32_t*)(sm + 16896);
#pragma unroll
    for (int nb = 0; nb < 8; nb++) {
        int cslot = nb * 4 + (lane & 3);
        uint32_t p0, p1;
        uint32_t h0 = packp(cacc[nb][0], cacc[nb][1], p0);
        uint32_t h1 = packp(cacc[nb][2], cacc[nb][3], p1);
        s1[rA * 33 + cslot] = h0;
        s2[rA * 33 + cslot] = p0;
        s1[(rA + 8) * 33 + cslot] = h1;
        s2[(rA + 8) * 33 + cslot] = p1;
    }
    __syncthreads();
    uint32_t* d1 = (uint32_t*)(g_Q1 + ((size_t)(b * 8 + h) * S_LEN + srow0) * 64);
    uint32_t* d2 = (uint32_t*)(g_Q2 + ((size_t)(b * 8 + h) * S_LEN + srow0) * 64);
#pragma unroll
    for (int q = 0; q < 16; q++) {
        int linear = q * 256 + tid;
        int row = linear >> 5, c = linear & 31;
        d1[row * 32 + c] = s1[row * 33 + c];
        d2[row * 32 + c] = s2[row * 33 + c];
    }
}

// ---------------- attn_pairs: pairs + 2-plane Gram, occ 3 -----------------
// smem: QS1 16K | QS2 16K | QT1 16K | QT2 16K | CUI 1K | CUJ 1K = 67584 B
// STG_D/STG_N (4K each) ALIAS into QS1 (dead after A-frag register load).
#define AP_QS1 0
#define AP_QS2 16384
#define AP_QT1 32768
#define AP_QT2 49152
#define AP_CUI  65536
#define AP_CUJ  66560
#define AP_STGD 0
#define AP_STGN 4096
#define AP_SMEM 67584

__global__ __launch_bounds__(256, 3) void attn_pairs() {
    extern __shared__ char sm[];
    uint32_t sb = smem_u32(sm);
    int tid = threadIdx.x;
    int lane = tid & 31, w = tid >> 5;
    int bid = blockIdx.x;
    int bh = bid / 136;
    int p = bid - bh * 136;
    int i = 0;
    while (p >= 16 - i) { p -= 16 - i; i++; }
    int j = i + p;
    int bhS = bh * S_LEN;

    const __nv_bfloat16* q1B = g_Q1 + (size_t)bhS * 64;
    const __nv_bfloat16* q2B = g_Q2 + (size_t)bhS * 64;
    const uint4* s1g = (const uint4*)(q1B + (size_t)(i * 128) * 64);
    const uint4* s2g = (const uint4*)(q2B + (size_t)(i * 128) * 64);
    const uint4* t1g = (const uint4*)(q1B + (size_t)(j * 128) * 64);
    const uint4* t2g = (const uint4*)(q2B + (size_t)(j * 128) * 64);

#pragma unroll
    for (int q = 0; q < 4; q++) {
        uint32_t idx = (uint32_t)(q * 256 + tid);
        uint32_t so = SW128(idx * 16);
        cp16(sb + AP_QS1 + so, s1g + idx);
        cp16(sb + AP_QS2 + so, s2g + idx);
        cp16(sb + AP_QT1 + so, t1g + idx);
        cp16(sb + AP_QT2 + so, t2g + idx);
    }
    if (tid < 64) {
        cp16(sb + AP_CUI + tid * 16, (const char*)(g_cu + bhS + i * 128) + tid * 16);
        cp16(sb + AP_CUJ + tid * 16, (const char*)(g_cu + bhS + j * 128) + tid * 16);
    }
    cp_commit();
    cp_wait<0>();
    __syncthreads();

    int row_a = w * 16 + (lane & 15);
    uint32_t a_sw = (uint32_t)((row_a & 7) << 4);
    uint32_t a_hi16 = (uint32_t)((lane >> 4) * 16);
    int nrow_base = (lane & 7) + ((lane >> 4) << 3);
    uint32_t b_sw = (uint32_t)((lane & 7) << 4);
    uint32_t b_c16 = (uint32_t)(((lane >> 3) & 1) * 16);

    // A fragments resident: 4 kk-chunks x 2 planes (QS smem dead afterwards)
    uint32_t a1[4][4], a2[4][4];
    uint32_t aB1 = sb + AP_QS1 + (uint32_t)row_a * 128;
    uint32_t aB2 = sb + AP_QS2 + (uint32_t)row_a * 128;
#pragma unroll
    for (int kk = 0; kk < 4; kk++) {
        uint32_t acol = ((uint32_t)(kk * 32) + a_hi16) ^ a_sw;
        ldsm4(a1[kk], aB1 + acol);
        ldsm4(a2[kk], aB2 + acol);
    }
    __syncthreads();   // all warps done reading QS before stg aliasing writes

    const float C1 = 0.25f * LOG2E;
    const float CA = C1 * (15.0f / 16.0f);
    const float CB = C1 * (1.0f / 16.0f);
    const float2* scuI = (const float2*)(sm + AP_CUI);
    const float2* scuJ = (const float2*)(sm + AP_CUJ);
    float* stgD = (float*)(sm + AP_STGD);   // [8][128] aliases QS1
    float* stgN = (float*)(sm + AP_STGN);
    int rA = w * 16 + (lane >> 2);
    float2 cuRA = scuI[rA];
    float2 cuRB = scuI[rA + 8];
    float cnA = cuRA.x, uAr = cuRA.y;
    float cnB = cuRB.x, uBr = cuRB.y;

    float den0 = 0.f, num0 = 0.f, den1 = 0.f, num1 = 0.f;
    bool offdiag = (i != j);

#pragma unroll
    for (int nb2 = 0; nb2 < 8; nb2++) {
        uint32_t nrow = (uint32_t)(nrow_base + nb2 * 16);
        float c1[2][4], c2[2][4];
#pragma unroll
        for (int nblk = 0; nblk < 2; nblk++)
#pragma unroll
            for (int r = 0; r < 4; r++) { c1[nblk][r] = 0.f; c2[nblk][r] = 0.f; }

#pragma unroll
        for (int kk = 0; kk < 4; kk++) {
            uint32_t boff = nrow * 128 + (((uint32_t)(kk * 32) + b_c16) ^ b_sw);
            uint32_t b1[4], b2[4];
            ldsm4(b1, sb + AP_QT1 + boff);
            ldsm4(b2, sb + AP_QT2 + boff);
            mma16816(c1[0], a1[kk], b1);
            mma16816(c1[1], a1[kk], b1 + 2);
            mma16816(c2[0], a2[kk], b2);
            mma16816(c2[1], a2[kk], b2 + 2);
        }

#pragma unroll
        for (int nblk = 0; nblk < 2; nblk++) {
            int nb = 2 * nb2 + nblk;
            int col0 = nb * 8 + (lane & 3) * 2;
            float2 cj0 = scuJ[col0];
            float2 cj1 = scuJ[col0 + 1];
            float w0 = ex2(fmaf(c1[nblk][0], CA, fmaf(c2[nblk][0], CB, cnA + cj0.x)));
            float w1 = ex2(fmaf(c1[nblk][1], CA, fmaf(c2[nblk][1], CB, cnA + cj1.x)));
            float w2 = ex2(fmaf(c1[nblk][2], CA, fmaf(c2[nblk][2], CB, cnB + cj0.x)));
            float w3 = ex2(fmaf(c1[nblk][3], CA, fmaf(c2[nblk][3], CB, cnB + cj1.x)));
            den0 += w0 + w1;
            num0 = fmaf(w0, cj0.y, fmaf(w1, cj1.y, num0));
            den1 += w2 + w3;
            num1 = fmaf(w2, cj0.y, fmaf(w3, cj1.y, num1));
            if (offdiag) {
                float pd0 = w0 + w2, pd1 = w1 + w3;
                float pn0 = fmaf(w0, uAr, w2 * uBr);
                float pn1 = fmaf(w1, uAr, w3 * uBr);
#pragma unroll
                for (int o = 4; o <= 16; o <<= 1) {
                    pd0 += __shfl_xor_sync(0xffffffffu, pd0, o);
                    pd1 += __shfl_xor_sync(0xffffffffu, pd1, o);
                    pn0 += __shfl_xor_sync(0xffffffffu, pn0, o);
                    pn1 += __shfl_xor_sync(0xffffffffu, pn1, o);
                }
                if (lane < 4) {
                    stgD[w * 128 + col0] = pd0;
                    stgD[w * 128 + col0 + 1] = pd1;
                    stgN[w * 128 + col0] = pn0;
                    stgN[w * 128 + col0 + 1] = pn1;
                }
            }
        }
    }

    // row-side reduce & write (slot j for rows of block i)
#pragma unroll
    for (int o = 1; o <= 2; o <<= 1) {
        den0 += __shfl_xor_sync(0xffffffffu, den0, o);
        num0 += __shfl_xor_sync(0xffffffffu, num0, o);
        den1 += __shfl_xor_sync(0xffffffffu, den1, o);
        num1 += __shfl_xor_sync(0xffffffffu, num1, o);
    }
    if ((lane & 3) == 0) {
        size_t gr = ((size_t)bhS + i * 128 + rA) * 16 + j;
        g_pd[gr] = den0;
        g_pn[gr] = num0;
        g_pd[gr + 8 * 16] = den1;
        g_pn[gr + 8 * 16] = num1;
    }

    // col-side reduce & write (slot i for rows of block j)
    if (offdiag) {
        __syncthreads();
        if (tid < 128) {
            float d = 0.f, n = 0.f;
#pragma unroll
            for (int ww = 0; ww < 8; ww++) {
                d += stgD[ww * 128 + tid];
                n += stgN[ww * 128 + tid];
            }
            size_t gr = ((size_t)bhS + j * 128 + tid) * 16 + i;
            g_pd[gr] = d;
            g_pn[gr] = n;
        }
    }
}

// ---------------- attn_final: out = sigmoid(sum(num)/sum(den)) ------------
__global__ __launch_bounds__(256) void attn_final(float* __restrict__ out) {
    int r = blockIdx.x * 256 + threadIdx.x;   // 0..32767
    const float4* pd = (const float4*)(g_pd + (size_t)r * 16);
    const float4* pn = (const float4*)(g_pn + (size_t)r * 16);
    float d = 0.f, n = 0.f;
#pragma unroll
    for (int q = 0; q < 4; q++) {
        float4 vd = pd[q], vn = pn[q];
        d += (vd.x + vd.y) + (vd.z + vd.w);
        n += (vn.x + vn.y) + (vn.z + vn.w);
    }
    float z = n / d;
    out[r] = 1.0f / (1.0f + ex2(-z * LOG2E));
}

// ---------------- launch ----------------
extern "C" void kernel_launch(void* const* d_in, const int* in_sizes, int n_in,
                              void* d_out, int out_size) {
    const float *X = nullptr, *Wq = nullptr, *Wv = nullptr;
    for (int i = 0; i < n_in; i++) {
        if (in_sizes[i] == 2 * 2048 * 512)      X  = (const float*)d_in[i];
        else if (in_sizes[i] == 512 * 512)      Wq = (const float*)d_in[i];
        else if (in_sizes[i] == 512)            Wv = (const float*)d_in[i];
    }
    float* out = (float*)d_out;

    cudaFuncSetAttribute(gemm_q, cudaFuncAttributeMaxDynamicSharedMemorySize, GQ_SMEM);
    cudaFuncSetAttribute(attn_pairs, cudaFuncAttributeMaxDynamicSharedMemorySize, AP_SMEM);

    convert_w<<<256, 256>>>(Wq);
    calc_g<<<64, 256>>>(Wv);
    convert_x<<<1024, 256>>>(X);
    gemm_q<<<256, 256, GQ_SMEM>>>();
    attn_pairs<<<NBH * 136, 256, AP_SMEM>>>();
    attn_final<<<128, 256>>>(out);
}